// round 12
// baseline (speedup 1.0000x reference)
#include <cuda_runtime.h>
#include <cuda_bf16.h>
#include <math.h>
#include <stdint.h>

#define BB 16
#define SS 128
#define VV 40000
#define DD 768
#define HH 12
#define HD 64
#define FF 3072
#define LL 12

typedef __nv_bfloat16 bf16;

// ---------------- fp32 scratch ----------------
__device__ float g_h   [BB*SS*DD];
__device__ float g_qkv [BB*SS*3*DD];   // [which][b][h][s][e] head-contiguous
__device__ float g_proj[BB*SS*DD];
__device__ float g_ff2 [BB*SS*DD];
__device__ float g_bqkv[LL*3*DD];

#define QKV_PLANE (BB*SS*DD)

// ---------------- bf16 split weights [N][K] ----------------
__device__ bf16 s_wqkv[2][LL*3*DD*DD];
__device__ bf16 s_wo  [2][LL*DD*DD];
__device__ bf16 s_w1  [2][LL*DD*FF];
__device__ bf16 s_w2  [2][LL*FF*DD];
__device__ bf16 s_wout[2][VV*DD];
__device__ bf16 s_actA[2][BB*SS*FF];
__device__ bf16 s_actB[2][BB*SS*FF];

// ======================= helpers =======================
__device__ __forceinline__ uint32_t smem_u32(const void* p) {
    uint32_t a;
    asm("{ .reg .u64 t; cvta.to.shared.u64 t, %1; cvt.u32.u64 %0, t; }" : "=r"(a) : "l"(p));
    return a;
}
__device__ __forceinline__ void cp16(uint32_t dst, const void* src) {
    asm volatile("cp.async.cg.shared.global [%0], [%1], 16;" :: "r"(dst), "l"(src) : "memory");
}
__device__ __forceinline__ void zero16(uint32_t dst) {
    asm volatile("st.shared.v4.b32 [%0], {%1,%1,%1,%1};" :: "r"(dst), "r"(0u) : "memory");
}
__device__ __forceinline__ void cp_commit() {
    asm volatile("cp.async.commit_group;" ::: "memory");
}
__device__ __forceinline__ void ldm4(uint32_t addr, uint32_t* r) {
    asm volatile("ldmatrix.sync.aligned.m8n8.x4.shared.b16 {%0,%1,%2,%3}, [%4];"
                 : "=r"(r[0]), "=r"(r[1]), "=r"(r[2]), "=r"(r[3]) : "r"(addr));
}
__device__ __forceinline__ void mma16816(float* d, const uint32_t* a, uint32_t b0, uint32_t b1) {
    asm volatile(
        "mma.sync.aligned.m16n8k16.row.col.f32.bf16.bf16.f32 "
        "{%0,%1,%2,%3}, {%4,%5,%6,%7}, {%8,%9}, {%0,%1,%2,%3};"
        : "+f"(d[0]), "+f"(d[1]), "+f"(d[2]), "+f"(d[3])
        : "r"(a[0]), "r"(a[1]), "r"(a[2]), "r"(a[3]), "r"(b0), "r"(b1));
}
__device__ __forceinline__ void split_bf16(float v, bf16& h, bf16& l) {
    h = __float2bfloat16(v);
    l = __float2bfloat16(v - __bfloat162float(h));
}

#define TROW 80

// ======================= small kernels =======================
__global__ void embed_kernel(const int* __restrict__ x,
                             const float* __restrict__ bpe,
                             const float* __restrict__ pe,
                             bf16* __restrict__ ah, bf16* __restrict__ al) {
    int idx = blockIdx.x * blockDim.x + threadIdx.x;
    if (idx >= BB*SS*DD) return;
    int d  = idx % DD;
    int bs = idx / DD;
    int s  = bs % SS;
    int tok = x[bs];
    float v = bpe[(long)tok*DD + d] + pe[s*DD + d];
    g_h[idx] = v;
    bf16 h, l; split_bf16(v, h, l);
    ah[idx] = h; al[idx] = l;
}

__global__ void concat_bias(const float* __restrict__ bq, const float* __restrict__ bk,
                            const float* __restrict__ bv) {
    int idx = blockIdx.x * blockDim.x + threadIdx.x;
    if (idx >= LL*3*DD) return;
    int l = idx / (3*DD), n = idx % (3*DD);
    float v;
    if (n < DD)          v = bq[l*DD + n];
    else if (n < 2*DD)   v = bk[l*DD + n - DD];
    else                 v = bv[l*DD + n - 2*DD];
    g_bqkv[idx] = v;
}

// merged QKV weight transpose+split: z = which*(LL*HH) + l*HH + h
// src [l][h][D][HD] fp32 -> dst s_wqkv [l][which*DD + h*HD][D] bf16 hi/lo
__global__ void conv_qkv(const float* __restrict__ Wq, const float* __restrict__ Wk,
                         const float* __restrict__ Wv,
                         bf16* __restrict__ dhi, bf16* __restrict__ dlo) {
    __shared__ float t[32][36];
    int z = blockIdx.z;
    int which = z / (LL*HH);
    int rem = z % (LL*HH);
    const float* src = (which == 0) ? Wq : ((which == 1) ? Wk : Wv);
    long zs = (long)rem * DD * HD;                           // [l][h] plane in src
    int l = rem / HH, h = rem % HH;
    long zd = (long)l*3*DD*DD + (long)which*DD*DD + (long)h*HD*DD;

    int c0 = blockIdx.x * 32, r0 = blockIdx.y * 32;          // c: HD dim, r: D dim
    int tx = threadIdx.x, ty = threadIdx.y;                  // (32, 8)
    #pragma unroll
    for (int i = 0; i < 4; i++) {
        int row = ty + i * 8;
        t[tx][row] = src[zs + (long)(r0 + row) * HD + c0 + tx];
    }
    __syncthreads();
    int cc = ty + (tx >> 3) * 8;
    int r4 = (tx & 7) * 4;
    float4 v = *reinterpret_cast<const float4*>(&t[cc][r4]);
    bf16 h0,l0,h1,l1,h2,l2,h3,l3;
    split_bf16(v.x, h0, l0); split_bf16(v.y, h1, l1);
    split_bf16(v.z, h2, l2); split_bf16(v.w, h3, l3);
    long o = zd + (long)(c0 + cc) * DD + r0 + r4;
    __nv_bfloat162 hv0(h0, h1), hv1(h2, h3), lv0(l0, l1), lv1(l2, l3);
    uint2 hp, lp;
    hp.x = *reinterpret_cast<uint32_t*>(&hv0); hp.y = *reinterpret_cast<uint32_t*>(&hv1);
    lp.x = *reinterpret_cast<uint32_t*>(&lv0); lp.y = *reinterpret_cast<uint32_t*>(&lv1);
    *reinterpret_cast<uint2*>(&dhi[o]) = hp;
    *reinterpret_cast<uint2*>(&dlo[o]) = lp;
}

// generic transpose + split (for Wo/W1/W2/Wout)
__global__ void conv_transpose(const float* __restrict__ src, bf16* __restrict__ dhi,
                               bf16* __restrict__ dlo, int R, int C,
                               long srcZ, long dstZ) {
    __shared__ float t[32][36];
    int c0 = blockIdx.x * 32, r0 = blockIdx.y * 32;
    long zs = (long)blockIdx.z * srcZ;
    long zd = (long)blockIdx.z * dstZ;
    int tx = threadIdx.x, ty = threadIdx.y;
    #pragma unroll
    for (int i = 0; i < 4; i++) {
        int row = ty + i * 8;
        t[tx][row] = src[zs + (long)(r0 + row) * C + c0 + tx];
    }
    __syncthreads();
    int cc = ty + (tx >> 3) * 8;
    int r4 = (tx & 7) * 4;
    float4 v = *reinterpret_cast<const float4*>(&t[cc][r4]);
    bf16 h0,l0,h1,l1,h2,l2,h3,l3;
    split_bf16(v.x, h0, l0); split_bf16(v.y, h1, l1);
    split_bf16(v.z, h2, l2); split_bf16(v.w, h3, l3);
    long o = zd + (long)(c0 + cc) * R + r0 + r4;
    __nv_bfloat162 hv0(h0, h1), hv1(h2, h3), lv0(l0, l1), lv1(l2, l3);
    uint2 hp, lp;
    hp.x = *reinterpret_cast<uint32_t*>(&hv0); hp.y = *reinterpret_cast<uint32_t*>(&hv1);
    lp.x = *reinterpret_cast<uint32_t*>(&lv0); lp.y = *reinterpret_cast<uint32_t*>(&lv1);
    *reinterpret_cast<uint2*>(&dhi[o]) = hp;
    *reinterpret_cast<uint2*>(&dlo[o]) = lp;
}

// ======================= HMMA split-bf16 GEMM (proven config) =======================
template<int TM>
__device__ __forceinline__ void load_chunk(
    uint32_t base, const bf16* __restrict__ Ah, const bf16* __restrict__ Al,
    const bf16* __restrict__ Bh, const bf16* __restrict__ Bl,
    int m0, int n0, int N, int K, int c, int tid)
{
    const uint32_t A_BYTES = TM * TROW;
    const uint32_t BUF = (2 * TM + 256) * TROW;
    uint32_t bb = base + (uint32_t)(c & 1) * BUF;
    int k0 = c << 5;
    #pragma unroll
    for (int i = 0; i < TM/64; i++) {
        int ci  = tid + i * 256;
        int row = ci >> 2, kq = ci & 3;
        uint32_t doff = (uint32_t)(row * TROW + kq * 16);
        long aoff = (long)(m0 + row) * K + k0 + kq * 8;
        cp16(bb + doff, Ah + aoff);
        cp16(bb + A_BYTES + doff, Al + aoff);
    }
    #pragma unroll
    for (int i = 0; i < 2; i++) {
        int ci  = tid + i * 256;
        int row = ci >> 2, kq = ci & 3;
        uint32_t doff = (uint32_t)(row * TROW + kq * 16);
        int nr = n0 + row;
        if (nr < N) {
            long boff = (long)nr * K + k0 + kq * 8;
            cp16(bb + 2*A_BYTES + doff, Bh + boff);
            cp16(bb + 2*A_BYTES + 128*TROW + doff, Bl + boff);
        } else {
            zero16(bb + 2*A_BYTES + doff);
            zero16(bb + 2*A_BYTES + 128*TROW + doff);
        }
    }
}

__device__ __forceinline__ long qkv_addr(int row, int col) {
    int b = row >> 7, s = row & (SS - 1);
    int which = col / DD;
    int rem = col - which * DD;
    int h = rem >> 6, e = rem & 63;
    return (long)which * QKV_PLANE + (((long)(b * HH + h) * SS + s) * HD) + e;
}

template<int MI, int OUT>
__global__ __launch_bounds__(256, 2) void gemm_hmma(
    const bf16* __restrict__ Ah, const bf16* __restrict__ Al,
    const bf16* __restrict__ Bh, const bf16* __restrict__ Bl,
    const float* __restrict__ bias, float* __restrict__ C,
    bf16* __restrict__ Oh, bf16* __restrict__ Ol,
    int N, int K)
{
    constexpr int TM = MI * 32;
    const uint32_t A_BYTES = TM * TROW;
    const uint32_t BUF = (2 * TM + 256) * TROW;
    extern __shared__ char smem[];
    const uint32_t base = smem_u32(smem);
    const int tid  = threadIdx.x;
    const int lane = tid & 31;
    const int w    = tid >> 5;
    const int wm   = w & 1;
    const int wn   = w >> 1;
    const int m0 = blockIdx.x * TM, n0 = blockIdx.y * 128;
    const int nCh = K >> 5;

    float acc[MI][4][4];
    #pragma unroll
    for (int i = 0; i < MI; i++)
        #pragma unroll
        for (int j = 0; j < 4; j++)
            #pragma unroll
            for (int q = 0; q < 4; q++) acc[i][j][q] = 0.f;

    const uint32_t a_loff = (uint32_t)((lane & 15) * TROW + ((lane >> 4) << 3) * 2);
    const uint32_t b_loff = (uint32_t)((((lane & 7) + ((lane & 16) ? 8 : 0)) * TROW) +
                                       ((lane & 8) ? 16 : 0));

    load_chunk<TM>(base, Ah, Al, Bh, Bl, m0, n0, N, K, 0, tid);
    cp_commit();

    for (int c = 0; c < nCh; c++) {
        if (c + 1 < nCh) {
            load_chunk<TM>(base, Ah, Al, Bh, Bl, m0, n0, N, K, c + 1, tid);
            cp_commit();
            asm volatile("cp.async.wait_group 1;" ::: "memory");
        } else {
            asm volatile("cp.async.wait_group 0;" ::: "memory");
        }
        __syncthreads();

        uint32_t bb = base + (uint32_t)(c & 1) * BUF;
        uint32_t aH = bb + (uint32_t)(wm * (MI * 16)) * TROW;
        uint32_t aL = aH + A_BYTES;
        uint32_t bH = bb + 2 * A_BYTES + (uint32_t)(wn * 32) * TROW;
        uint32_t bL = bH + 128 * TROW;

        #pragma unroll
        for (int ks = 0; ks < 2; ks++) {
            const uint32_t koff = (uint32_t)(ks * 32);
            uint32_t bh[2][4], bl[2][4];
            #pragma unroll
            for (int g = 0; g < 2; g++) {
                ldm4(bH + (uint32_t)(g * 16) * TROW + b_loff + koff, bh[g]);
                ldm4(bL + (uint32_t)(g * 16) * TROW + b_loff + koff, bl[g]);
            }
            #pragma unroll
            for (int mi = 0; mi < MI; mi++) {
                uint32_t ah[4], al[4];
                ldm4(aH + (uint32_t)(mi * 16) * TROW + a_loff + koff, ah);
                ldm4(aL + (uint32_t)(mi * 16) * TROW + a_loff + koff, al);
                #pragma unroll
                for (int ni = 0; ni < 4; ni++) {
                    const int g = ni >> 1, o = (ni & 1) * 2;
                    mma16816(acc[mi][ni], ah, bh[g][o], bh[g][o + 1]);
                    mma16816(acc[mi][ni], ah, bl[g][o], bl[g][o + 1]);
                    mma16816(acc[mi][ni], al, bh[g][o], bh[g][o + 1]);
                }
            }
        }
        __syncthreads();
    }

    // epilogue
    #pragma unroll
    for (int mi = 0; mi < MI; mi++) {
        int row = m0 + wm * (MI * 16) + mi * 16 + (lane >> 2);
        #pragma unroll
        for (int ni = 0; ni < 4; ni++) {
            int col = n0 + wn * 32 + ni * 8 + ((lane & 3) << 1);
            if (col < N) {
                float bx = bias[col], by = bias[col + 1];
                float v00 = acc[mi][ni][0] + bx, v01 = acc[mi][ni][1] + by;
                float v10 = acc[mi][ni][2] + bx, v11 = acc[mi][ni][3] + by;
                if (OUT == 0) {
                    *reinterpret_cast<float2*>(C + (long)row * N + col)       = make_float2(v00, v01);
                    *reinterpret_cast<float2*>(C + (long)(row + 8) * N + col) = make_float2(v10, v11);
                } else if (OUT == 2) {
                    long a0 = qkv_addr(row, col);
                    *reinterpret_cast<float2*>(C + a0)          = make_float2(v00, v01);
                    *reinterpret_cast<float2*>(C + a0 + 8 * HD) = make_float2(v10, v11);
                } else {
                    bf16 h0,l0,h1,l1,h2,l2,h3,l3;
                    split_bf16(v00, h0, l0); split_bf16(v01, h1, l1);
                    split_bf16(v10, h2, l2); split_bf16(v11, h3, l3);
                    *reinterpret_cast<__nv_bfloat162*>(Oh + (long)row * N + col)       = __nv_bfloat162(h0, h1);
                    *reinterpret_cast<__nv_bfloat162*>(Ol + (long)row * N + col)       = __nv_bfloat162(l0, l1);
                    *reinterpret_cast<__nv_bfloat162*>(Oh + (long)(row + 8) * N + col) = __nv_bfloat162(h2, h3);
                    *reinterpret_cast<__nv_bfloat162*>(Ol + (long)(row + 8) * N + col) = __nv_bfloat162(l2, l3);
                }
            }
        }
    }
}

// ======================= attention v4: per-query block, full 128-thread AV =======================
__global__ __launch_bounds__(128) void attn_kernel4(const int* __restrict__ ignore,
                                                    bf16* __restrict__ oh,
                                                    bf16* __restrict__ ol) {
    const int qi = blockIdx.x & (SS - 1);
    const int h  = (blockIdx.x >> 7) % HH;
    const int b  = blockIdx.x / (SS * HH);
    const int t  = threadIdx.x;

    __shared__ float qrow[HD];
    __shared__ float p[SS];
    __shared__ float red[SS];

    const long headoff = (long)(b * HH + h) * SS * HD;
    const float* Q = g_qkv + 0L * QKV_PLANE + headoff;
    const float* K = g_qkv + 1L * QKV_PLANE + headoff;
    const float* V = g_qkv + 2L * QKV_PLANE + headoff;

    if (t < HD) qrow[t] = Q[(long)qi * HD + t];
    __syncthreads();

    const bool allowed = (t <= qi) && (ignore[b * SS + t] == 0 || t == qi);
    float score = -INFINITY;
    if (allowed) {
        const float* kptr = K + (long)t * HD;
        float s = 0.f;
        #pragma unroll
        for (int e = 0; e < HD; e += 4) {
            float4 kv = *reinterpret_cast<const float4*>(kptr + e);
            s += qrow[e]*kv.x + qrow[e+1]*kv.y + qrow[e+2]*kv.z + qrow[e+3]*kv.w;
        }
        score = s * 0.125f;
    }
    red[t] = score; __syncthreads();
    for (int off = 64; off > 0; off >>= 1) {
        if (t < off) red[t] = fmaxf(red[t], red[t + off]);
        __syncthreads();
    }
    const float mx = red[0];
    __syncthreads();
    const float e = allowed ? expf(score - mx) : 0.f;
    p[t] = e; red[t] = e; __syncthreads();
    for (int off = 64; off > 0; off >>= 1) {
        if (t < off) red[t] += red[t + off];
        __syncthreads();
    }
    const float inv = 1.f / red[0];
    __syncthreads();   // red[] about to be reused

    // AV: all 128 threads. e = t & 63, k-parity = t >> 6; combine halves via red[].
    {
        const int e = t & 63;
        const int par = t >> 6;
        const float* vbase = V + e;
        float o = 0.f;
        for (int k = par; k <= qi; k += 2) o += p[k] * vbase[(long)k * HD];
        red[t] = o;
        __syncthreads();
        if (t < HD) {
            float r = (red[t] + red[t + 64]) * inv;
            long oidx = (long)(b * SS + qi) * DD + h * HD + t;
            bf16 hh, ll; split_bf16(r, hh, ll);
            oh[oidx] = hh; ol[oidx] = ll;
        }
    }
}

// ======================= residual (+GELU) + LayerNorm + split, single-pass =======================
__global__ __launch_bounds__(256) void add_ln_kernel(
    const float* __restrict__ res_in,
    const float* __restrict__ w, const float* __restrict__ bvec,
    bf16* __restrict__ ah, bf16* __restrict__ al,
    int dogelu) {
    const int row = blockIdx.x;
    const int t = threadIdx.x;
    __shared__ float rs1[8], rs2[8];

    float vals[3];
    float s1 = 0.f, s2 = 0.f;
    #pragma unroll
    for (int i = 0; i < 3; i++) {
        int d = t + i * 256;
        float r = res_in[(long)row * DD + d];
        if (dogelu) r = 0.5f * r * (1.f + erff(r * 0.70710678118f));
        float v = g_h[(long)row * DD + d] + r;
        vals[i] = v;
        s1 += v;
        s2 += v * v;
    }
    #pragma unroll
    for (int off = 16; off > 0; off >>= 1) {
        s1 += __shfl_xor_sync(0xffffffff, s1, off);
        s2 += __shfl_xor_sync(0xffffffff, s2, off);
    }
    if ((t & 31) == 0) { rs1[t >> 5] = s1; rs2[t >> 5] = s2; }
    __syncthreads();
    if (t < 32) {
        float a = (t < 8) ? rs1[t] : 0.f;
        float bq_ = (t < 8) ? rs2[t] : 0.f;
        #pragma unroll
        for (int off = 4; off > 0; off >>= 1) {
            a  += __shfl_xor_sync(0xffffffff, a, off);
            bq_ += __shfl_xor_sync(0xffffffff, bq_, off);
        }
        if (t == 0) { rs1[0] = a; rs2[0] = bq_; }
    }
    __syncthreads();
    const float mean = rs1[0] * (1.f / DD);
    const float var  = rs2[0] * (1.f / DD) - mean * mean;
    const float rstd = rsqrtf(var + 1e-5f);

    #pragma unroll
    for (int i = 0; i < 3; i++) {
        int d = t + i * 256;
        float v = (vals[i] - mean) * rstd * w[d] + bvec[d];
        g_h[(long)row * DD + d] = v;
        bf16 hh, ll; split_bf16(v, hh, ll);
        ah[(long)row * DD + d] = hh;
        al[(long)row * DD + d] = ll;
    }
}

// ======================= host orchestration =======================
extern "C" void kernel_launch(void* const* d_in, const int* in_sizes, int n_in,
                              void* d_out, int out_size) {
    const int*   x    = (const int*)  d_in[0];
    const int*   ign  = (const int*)  d_in[1];
    const float* bpe  = (const float*)d_in[2];
    const float* pe   = (const float*)d_in[3];
    const float* Wq   = (const float*)d_in[4];
    const float* bq   = (const float*)d_in[5];
    const float* Wk   = (const float*)d_in[6];
    const float* bk   = (const float*)d_in[7];
    const float* Wv   = (const float*)d_in[8];
    const float* bv   = (const float*)d_in[9];
    const float* Wo   = (const float*)d_in[10];
    const float* bo   = (const float*)d_in[11];
    const float* W1   = (const float*)d_in[12];
    const float* b1   = (const float*)d_in[13];
    const float* W2   = (const float*)d_in[14];
    const float* b2   = (const float*)d_in[15];
    const float* ln1w = (const float*)d_in[16];
    const float* ln1b = (const float*)d_in[17];
    const float* ln2w = (const float*)d_in[18];
    const float* ln2b = (const float*)d_in[19];
    const float* Wout = (const float*)d_in[20];
    const float* bout = (const float*)d_in[21];
    float* out = (float*)d_out;

    float *gh, *gqkv, *gproj, *gff2, *gbqkv;
    cudaGetSymbolAddress((void**)&gh,    g_h);
    cudaGetSymbolAddress((void**)&gqkv,  g_qkv);
    cudaGetSymbolAddress((void**)&gproj, g_proj);
    cudaGetSymbolAddress((void**)&gff2,  g_ff2);
    cudaGetSymbolAddress((void**)&gbqkv, g_bqkv);

    bf16 *wqkv_h, *wo_h, *w1_h, *w2_h, *wout_h, *actA_h, *actB_h;
    bf16 *wqkv_l, *wo_l, *w1_l, *w2_l, *wout_l, *actA_l, *actB_l;
    void* p;
    cudaGetSymbolAddress(&p, s_wqkv); wqkv_h = (bf16*)p; wqkv_l = wqkv_h + (long)LL*3*DD*DD;
    cudaGetSymbolAddress(&p, s_wo);   wo_h = (bf16*)p;   wo_l   = wo_h   + (long)LL*DD*DD;
    cudaGetSymbolAddress(&p, s_w1);   w1_h = (bf16*)p;   w1_l   = w1_h   + (long)LL*DD*FF;
    cudaGetSymbolAddress(&p, s_w2);   w2_h = (bf16*)p;   w2_l   = w2_h   + (long)LL*FF*DD;
    cudaGetSymbolAddress(&p, s_wout); wout_h = (bf16*)p; wout_l = wout_h + (long)VV*DD;
    cudaGetSymbolAddress(&p, s_actA); actA_h = (bf16*)p; actA_l = actA_h + (long)BB*SS*FF;
    cudaGetSymbolAddress(&p, s_actB); actB_h = (bf16*)p; actB_l = actB_h + (long)BB*SS*FF;

    const int SM128 = (2*128 + 256) * TROW * 2;   // 81920
    const int SM64  = (2*64  + 256) * TROW * 2;   // 61440
    cudaFuncSetAttribute(gemm_hmma<4,2>, cudaFuncAttributeMaxDynamicSharedMemorySize, SM128);
    cudaFuncSetAttribute(gemm_hmma<4,0>, cudaFuncAttributeMaxDynamicSharedMemorySize, SM128);
    cudaFuncSetAttribute(gemm_hmma<4,1>, cudaFuncAttributeMaxDynamicSharedMemorySize, SM128);
    cudaFuncSetAttribute(gemm_hmma<2,0>, cudaFuncAttributeMaxDynamicSharedMemorySize, SM64);

    const int M = BB * SS;  // 2048
    dim3 tb32(32, 8);

    // launches: embed(0), concat(1), conv_qkv(2), QKV-gemm(3) <- ncu capture slot
    embed_kernel<<<(BB*SS*DD + 255)/256, 256>>>(x, bpe, pe, actA_h, actA_l);
    concat_bias<<<(LL*3*DD + 255)/256, 256>>>(bq, bk, bv);
    conv_qkv<<<dim3(HD/32, DD/32, 3*LL*HH), tb32>>>(Wq, Wk, Wv, wqkv_h, wqkv_l);

    gemm_hmma<4,2><<<dim3(M/128, (3*DD)/128), 256, SM128>>>(actA_h, actA_l,
        wqkv_h, wqkv_l, gbqkv, gqkv, nullptr, nullptr, 3*DD, DD);

    // remaining weight conversions (complete before first use below)
    conv_transpose<<<dim3(DD/32, DD/32, LL), tb32>>>(Wo, wo_h, wo_l,
        DD, DD, (long)DD*DD, (long)DD*DD);
    conv_transpose<<<dim3(FF/32, DD/32, LL), tb32>>>(W1, w1_h, w1_l,
        DD, FF, (long)DD*FF, (long)DD*FF);
    conv_transpose<<<dim3(DD/32, FF/32, LL), tb32>>>(W2, w2_h, w2_l,
        FF, DD, (long)FF*DD, (long)FF*DD);
    conv_transpose<<<dim3(VV/32, DD/32, 1), tb32>>>(Wout, wout_h, wout_l,
        DD, VV, 0, 0);

    for (int l = 0; l < LL; l++) {
        if (l > 0) {
            gemm_hmma<4,2><<<dim3(M/128, (3*DD)/128), 256, SM128>>>(actA_h, actA_l,
                wqkv_h + (long)l*3*DD*DD, wqkv_l + (long)l*3*DD*DD,
                gbqkv + (long)l*3*DD, gqkv, nullptr, nullptr, 3*DD, DD);
        }

        attn_kernel4<<<BB*HH*SS, 128>>>(ign, actB_h, actB_l);

        gemm_hmma<2,0><<<dim3(M/64, DD/128), 256, SM64>>>(actB_h, actB_l,
            wo_h + (long)l*DD*DD, wo_l + (long)l*DD*DD,
            bo + (long)l*DD, gproj, nullptr, nullptr, DD, DD);
        add_ln_kernel<<<M, 256>>>(gproj, ln1w + (long)l*DD, ln1b + (long)l*DD,
                                  actA_h, actA_l, 0);

        gemm_hmma<4,1><<<dim3(M/128, FF/128), 256, SM128>>>(actA_h, actA_l,
            w1_h + (long)l*DD*FF, w1_l + (long)l*DD*FF,
            b1 + (long)l*FF, nullptr, actB_h, actB_l, FF, DD);
        gemm_hmma<2,0><<<dim3(M/64, DD/128), 256, SM64>>>(actB_h, actB_l,
            w2_h + (long)l*FF*DD, w2_l + (long)l*FF*DD,
            b2 + (long)l*DD, gff2, nullptr, nullptr, DD, FF);
        add_ln_kernel<<<M, 256>>>(gff2, ln2w + (long)l*DD, ln2b + (long)l*DD,
                                  actA_h, actA_l, 1);
    }

    gemm_hmma<4,0><<<dim3(M/128, (VV + 127)/128), 256, SM128>>>(actA_h, actA_l,
        wout_h, wout_l, bout, out, nullptr, nullptr, VV, DD);
}

// round 13
// speedup vs baseline: 1.0253x; 1.0253x over previous
#include <cuda_runtime.h>
#include <cuda_bf16.h>
#include <math.h>
#include <stdint.h>

#define BB 16
#define SS 128
#define VV 40000
#define DD 768
#define HH 12
#define HD 64
#define FF 3072
#define LL 12

typedef __nv_bfloat16 bf16;

// ---------------- fp32 scratch ----------------
__device__ float g_h   [BB*SS*DD];
__device__ float g_qkv [BB*SS*3*DD];   // [which][b][h][s][e] head-contiguous
__device__ float g_proj[2*BB*SS*DD];   // split-K partials
__device__ float g_ff2 [2*BB*SS*DD];
__device__ float g_bqkv[LL*3*DD];

#define QKV_PLANE (BB*SS*DD)

// ---------------- bf16 split weights [N][K] ----------------
__device__ bf16 s_wqkv[2][LL*3*DD*DD];
__device__ bf16 s_wo  [2][LL*DD*DD];
__device__ bf16 s_w1  [2][LL*DD*FF];
__device__ bf16 s_w2  [2][LL*FF*DD];
__device__ bf16 s_wout[2][VV*DD];
__device__ bf16 s_actA[2][BB*SS*FF];
__device__ bf16 s_actB[2][BB*SS*FF];

// ======================= helpers =======================
__device__ __forceinline__ uint32_t smem_u32(const void* p) {
    uint32_t a;
    asm("{ .reg .u64 t; cvta.to.shared.u64 t, %1; cvt.u32.u64 %0, t; }" : "=r"(a) : "l"(p));
    return a;
}
__device__ __forceinline__ void cp16(uint32_t dst, const void* src) {
    asm volatile("cp.async.cg.shared.global [%0], [%1], 16;" :: "r"(dst), "l"(src) : "memory");
}
__device__ __forceinline__ void zero16(uint32_t dst) {
    asm volatile("st.shared.v4.b32 [%0], {%1,%1,%1,%1};" :: "r"(dst), "r"(0u) : "memory");
}
__device__ __forceinline__ void cp_commit() {
    asm volatile("cp.async.commit_group;" ::: "memory");
}
__device__ __forceinline__ void ldm4(uint32_t addr, uint32_t* r) {
    asm volatile("ldmatrix.sync.aligned.m8n8.x4.shared.b16 {%0,%1,%2,%3}, [%4];"
                 : "=r"(r[0]), "=r"(r[1]), "=r"(r[2]), "=r"(r[3]) : "r"(addr));
}
__device__ __forceinline__ void mma16816(float* d, const uint32_t* a, uint32_t b0, uint32_t b1) {
    asm volatile(
        "mma.sync.aligned.m16n8k16.row.col.f32.bf16.bf16.f32 "
        "{%0,%1,%2,%3}, {%4,%5,%6,%7}, {%8,%9}, {%0,%1,%2,%3};"
        : "+f"(d[0]), "+f"(d[1]), "+f"(d[2]), "+f"(d[3])
        : "r"(a[0]), "r"(a[1]), "r"(a[2]), "r"(a[3]), "r"(b0), "r"(b1));
}
__device__ __forceinline__ void split_bf16(float v, bf16& h, bf16& l) {
    h = __float2bfloat16(v);
    l = __float2bfloat16(v - __bfloat162float(h));
}

#define TROW 80

// ======================= small kernels =======================
__global__ void embed_kernel(const int* __restrict__ x,
                             const float* __restrict__ bpe,
                             const float* __restrict__ pe,
                             bf16* __restrict__ ah, bf16* __restrict__ al) {
    int idx = blockIdx.x * blockDim.x + threadIdx.x;
    if (idx >= BB*SS*DD) return;
    int d  = idx % DD;
    int bs = idx / DD;
    int s  = bs % SS;
    int tok = x[bs];
    float v = bpe[(long)tok*DD + d] + pe[s*DD + d];
    g_h[idx] = v;
    bf16 h, l; split_bf16(v, h, l);
    ah[idx] = h; al[idx] = l;
}

__global__ void concat_bias(const float* __restrict__ bq, const float* __restrict__ bk,
                            const float* __restrict__ bv) {
    int idx = blockIdx.x * blockDim.x + threadIdx.x;
    if (idx >= LL*3*DD) return;
    int l = idx / (3*DD), n = idx % (3*DD);
    float v;
    if (n < DD)          v = bq[l*DD + n];
    else if (n < 2*DD)   v = bk[l*DD + n - DD];
    else                 v = bv[l*DD + n - 2*DD];
    g_bqkv[idx] = v;
}

// merged QKV weight transpose+split
__global__ void conv_qkv(const float* __restrict__ Wq, const float* __restrict__ Wk,
                         const float* __restrict__ Wv,
                         bf16* __restrict__ dhi, bf16* __restrict__ dlo) {
    __shared__ float t[32][36];
    int z = blockIdx.z;
    int which = z / (LL*HH);
    int rem = z % (LL*HH);
    const float* src = (which == 0) ? Wq : ((which == 1) ? Wk : Wv);
    long zs = (long)rem * DD * HD;
    int l = rem / HH, h = rem % HH;
    long zd = (long)l*3*DD*DD + (long)which*DD*DD + (long)h*HD*DD;

    int c0 = blockIdx.x * 32, r0 = blockIdx.y * 32;
    int tx = threadIdx.x, ty = threadIdx.y;
    #pragma unroll
    for (int i = 0; i < 4; i++) {
        int row = ty + i * 8;
        t[tx][row] = src[zs + (long)(r0 + row) * HD + c0 + tx];
    }
    __syncthreads();
    int cc = ty + (tx >> 3) * 8;
    int r4 = (tx & 7) * 4;
    float4 v = *reinterpret_cast<const float4*>(&t[cc][r4]);
    bf16 h0,l0,h1,l1,h2,l2,h3,l3;
    split_bf16(v.x, h0, l0); split_bf16(v.y, h1, l1);
    split_bf16(v.z, h2, l2); split_bf16(v.w, h3, l3);
    long o = zd + (long)(c0 + cc) * DD + r0 + r4;
    __nv_bfloat162 hv0(h0, h1), hv1(h2, h3), lv0(l0, l1), lv1(l2, l3);
    uint2 hp, lp;
    hp.x = *reinterpret_cast<uint32_t*>(&hv0); hp.y = *reinterpret_cast<uint32_t*>(&hv1);
    lp.x = *reinterpret_cast<uint32_t*>(&lv0); lp.y = *reinterpret_cast<uint32_t*>(&lv1);
    *reinterpret_cast<uint2*>(&dhi[o]) = hp;
    *reinterpret_cast<uint2*>(&dlo[o]) = lp;
}

// generic transpose + split (Wo/W1/W2/Wout)
__global__ void conv_transpose(const float* __restrict__ src, bf16* __restrict__ dhi,
                               bf16* __restrict__ dlo, int R, int C,
                               long srcZ, long dstZ) {
    __shared__ float t[32][36];
    int c0 = blockIdx.x * 32, r0 = blockIdx.y * 32;
    long zs = (long)blockIdx.z * srcZ;
    long zd = (long)blockIdx.z * dstZ;
    int tx = threadIdx.x, ty = threadIdx.y;
    #pragma unroll
    for (int i = 0; i < 4; i++) {
        int row = ty + i * 8;
        t[tx][row] = src[zs + (long)(r0 + row) * C + c0 + tx];
    }
    __syncthreads();
    int cc = ty + (tx >> 3) * 8;
    int r4 = (tx & 7) * 4;
    float4 v = *reinterpret_cast<const float4*>(&t[cc][r4]);
    bf16 h0,l0,h1,l1,h2,l2,h3,l3;
    split_bf16(v.x, h0, l0); split_bf16(v.y, h1, l1);
    split_bf16(v.z, h2, l2); split_bf16(v.w, h3, l3);
    long o = zd + (long)(c0 + cc) * R + r0 + r4;
    __nv_bfloat162 hv0(h0, h1), hv1(h2, h3), lv0(l0, l1), lv1(l2, l3);
    uint2 hp, lp;
    hp.x = *reinterpret_cast<uint32_t*>(&hv0); hp.y = *reinterpret_cast<uint32_t*>(&hv1);
    lp.x = *reinterpret_cast<uint32_t*>(&lv0); lp.y = *reinterpret_cast<uint32_t*>(&lv1);
    *reinterpret_cast<uint2*>(&dhi[o]) = hp;
    *reinterpret_cast<uint2*>(&dlo[o]) = lp;
}

// ======================= HMMA split-bf16 GEMM (proven config + split-K) =======================
// A row stride = lda; per-CTA K span = Kloop, k-offset = blockIdx.z*Kloop.
// C partial plane stride = Cz. Bias added on z==0 only.
__device__ __forceinline__ void load_chunk(
    uint32_t base, const bf16* __restrict__ Ah, const bf16* __restrict__ Al,
    const bf16* __restrict__ Bh, const bf16* __restrict__ Bl,
    int m0, int n0, int N, int lda, int c, int tid)
{
    const uint32_t A_BYTES = 128 * TROW;
    const uint32_t BUF = (2 * 128 + 256) * TROW;
    uint32_t bb = base + (uint32_t)(c & 1) * BUF;
    int k0 = c << 5;
    #pragma unroll
    for (int i = 0; i < 2; i++) {
        int ci  = tid + i * 256;
        int row = ci >> 2, kq = ci & 3;
        uint32_t doff = (uint32_t)(row * TROW + kq * 16);
        long aoff = (long)(m0 + row) * lda + k0 + kq * 8;
        cp16(bb + doff, Ah + aoff);
        cp16(bb + A_BYTES + doff, Al + aoff);
        int nr = n0 + row;
        if (nr < N) {
            long boff = (long)nr * lda + k0 + kq * 8;
            cp16(bb + 2*A_BYTES + doff, Bh + boff);
            cp16(bb + 2*A_BYTES + 128*TROW + doff, Bl + boff);
        } else {
            zero16(bb + 2*A_BYTES + doff);
            zero16(bb + 2*A_BYTES + 128*TROW + doff);
        }
    }
}

__device__ __forceinline__ long qkv_addr(int row, int col) {
    int b = row >> 7, s = row & (SS - 1);
    int which = col / DD;
    int rem = col - which * DD;
    int h = rem >> 6, e = rem & 63;
    return (long)which * QKV_PLANE + (((long)(b * HH + h) * SS + s) * HD) + e;
}

template<int OUT>
__global__ __launch_bounds__(256, 2) void gemm_hmma(
    const bf16* __restrict__ Ah, const bf16* __restrict__ Al,
    const bf16* __restrict__ Bh, const bf16* __restrict__ Bl,
    const float* __restrict__ bias, float* __restrict__ C,
    bf16* __restrict__ Oh, bf16* __restrict__ Ol,
    int N, int Kloop, int lda, long Cz)
{
    const uint32_t A_BYTES = 128 * TROW;
    const uint32_t BUF = (2 * 128 + 256) * TROW;
    extern __shared__ char smem[];
    const uint32_t base = smem_u32(smem);
    const int tid  = threadIdx.x;
    const int lane = tid & 31;
    const int w    = tid >> 5;
    const int wm   = w & 1;
    const int wn   = w >> 1;
    const int m0 = blockIdx.x * 128, n0 = blockIdx.y * 128;
    const int nCh = Kloop >> 5;
    const int kbase = blockIdx.z * Kloop;
    Ah += kbase; Al += kbase; Bh += kbase; Bl += kbase;
    const bool addb = (blockIdx.z == 0);

    float acc[4][4][4];
    #pragma unroll
    for (int i = 0; i < 4; i++)
        #pragma unroll
        for (int j = 0; j < 4; j++)
            #pragma unroll
            for (int q = 0; q < 4; q++) acc[i][j][q] = 0.f;

    const uint32_t a_loff = (uint32_t)((lane & 15) * TROW + ((lane >> 4) << 3) * 2);
    const uint32_t b_loff = (uint32_t)((((lane & 7) + ((lane & 16) ? 8 : 0)) * TROW) +
                                       ((lane & 8) ? 16 : 0));

    load_chunk(base, Ah, Al, Bh, Bl, m0, n0, N, lda, 0, tid);
    cp_commit();

    for (int c = 0; c < nCh; c++) {
        if (c + 1 < nCh) {
            load_chunk(base, Ah, Al, Bh, Bl, m0, n0, N, lda, c + 1, tid);
            cp_commit();
            asm volatile("cp.async.wait_group 1;" ::: "memory");
        } else {
            asm volatile("cp.async.wait_group 0;" ::: "memory");
        }
        __syncthreads();

        uint32_t bb = base + (uint32_t)(c & 1) * BUF;
        uint32_t aH = bb + (uint32_t)(wm * 64) * TROW;
        uint32_t aL = aH + A_BYTES;
        uint32_t bH = bb + 2 * A_BYTES + (uint32_t)(wn * 32) * TROW;
        uint32_t bL = bH + 128 * TROW;

        #pragma unroll
        for (int ks = 0; ks < 2; ks++) {
            const uint32_t koff = (uint32_t)(ks * 32);
            uint32_t bh[2][4], bl[2][4];
            #pragma unroll
            for (int g = 0; g < 2; g++) {
                ldm4(bH + (uint32_t)(g * 16) * TROW + b_loff + koff, bh[g]);
                ldm4(bL + (uint32_t)(g * 16) * TROW + b_loff + koff, bl[g]);
            }
            #pragma unroll
            for (int mi = 0; mi < 4; mi++) {
                uint32_t ah[4], al[4];
                ldm4(aH + (uint32_t)(mi * 16) * TROW + a_loff + koff, ah);
                ldm4(aL + (uint32_t)(mi * 16) * TROW + a_loff + koff, al);
                #pragma unroll
                for (int ni = 0; ni < 4; ni++) {
                    const int g = ni >> 1, o = (ni & 1) * 2;
                    mma16816(acc[mi][ni], ah, bh[g][o], bh[g][o + 1]);
                    mma16816(acc[mi][ni], ah, bl[g][o], bl[g][o + 1]);
                    mma16816(acc[mi][ni], al, bh[g][o], bh[g][o + 1]);
                }
            }
        }
        __syncthreads();
    }

    // epilogue
    float* Cp = C + (long)blockIdx.z * Cz;
    #pragma unroll
    for (int mi = 0; mi < 4; mi++) {
        int row = m0 + wm * 64 + mi * 16 + (lane >> 2);
        #pragma unroll
        for (int ni = 0; ni < 4; ni++) {
            int col = n0 + wn * 32 + ni * 8 + ((lane & 3) << 1);
            if (col < N) {
                float bx = addb ? bias[col] : 0.f;
                float by = addb ? bias[col + 1] : 0.f;
                float v00 = acc[mi][ni][0] + bx, v01 = acc[mi][ni][1] + by;
                float v10 = acc[mi][ni][2] + bx, v11 = acc[mi][ni][3] + by;
                if (OUT == 0) {
                    *reinterpret_cast<float2*>(Cp + (long)row * N + col)       = make_float2(v00, v01);
                    *reinterpret_cast<float2*>(Cp + (long)(row + 8) * N + col) = make_float2(v10, v11);
                } else if (OUT == 2) {
                    long a0 = qkv_addr(row, col);
                    *reinterpret_cast<float2*>(Cp + a0)          = make_float2(v00, v01);
                    *reinterpret_cast<float2*>(Cp + a0 + 8 * HD) = make_float2(v10, v11);
                } else {
                    bf16 h0,l0,h1,l1,h2,l2,h3,l3;
                    split_bf16(v00, h0, l0); split_bf16(v01, h1, l1);
                    split_bf16(v10, h2, l2); split_bf16(v11, h3, l3);
                    *reinterpret_cast<__nv_bfloat162*>(Oh + (long)row * N + col)       = __nv_bfloat162(h0, h1);
                    *reinterpret_cast<__nv_bfloat162*>(Ol + (long)row * N + col)       = __nv_bfloat162(l0, l1);
                    *reinterpret_cast<__nv_bfloat162*>(Oh + (long)(row + 8) * N + col) = __nv_bfloat162(h2, h3);
                    *reinterpret_cast<__nv_bfloat162*>(Ol + (long)(row + 8) * N + col) = __nv_bfloat162(l2, l3);
                }
            }
        }
    }
}

// ======================= attention v3: per-query block, head-contiguous KV =======================
__global__ __launch_bounds__(128) void attn_kernel3(const int* __restrict__ ignore,
                                                    bf16* __restrict__ oh,
                                                    bf16* __restrict__ ol) {
    const int qi = blockIdx.x & (SS - 1);
    const int h  = (blockIdx.x >> 7) % HH;
    const int b  = blockIdx.x / (SS * HH);
    const int t  = threadIdx.x;

    __shared__ float qrow[HD];
    __shared__ float p[SS];
    __shared__ float red[SS];

    const long headoff = (long)(b * HH + h) * SS * HD;
    const float* Q = g_qkv + 0L * QKV_PLANE + headoff;
    const float* K = g_qkv + 1L * QKV_PLANE + headoff;
    const float* V = g_qkv + 2L * QKV_PLANE + headoff;

    if (t < HD) qrow[t] = Q[(long)qi * HD + t];
    __syncthreads();

    const bool allowed = (t <= qi) && (ignore[b * SS + t] == 0 || t == qi);
    float score = -INFINITY;
    if (allowed) {
        const float* kptr = K + (long)t * HD;
        float s = 0.f;
        #pragma unroll
        for (int e = 0; e < HD; e += 4) {
            float4 kv = *reinterpret_cast<const float4*>(kptr + e);
            s += qrow[e]*kv.x + qrow[e+1]*kv.y + qrow[e+2]*kv.z + qrow[e+3]*kv.w;
        }
        score = s * 0.125f;
    }
    red[t] = score; __syncthreads();
    for (int off = 64; off > 0; off >>= 1) {
        if (t < off) red[t] = fmaxf(red[t], red[t + off]);
        __syncthreads();
    }
    const float mx = red[0];
    __syncthreads();
    const float e = allowed ? expf(score - mx) : 0.f;
    p[t] = e; red[t] = e; __syncthreads();
    for (int off = 64; off > 0; off >>= 1) {
        if (t < off) red[t] += red[t + off];
        __syncthreads();
    }
    const float inv = 1.f / red[0];
    if (t < HD) {
        const float* vbase = V + t;
        float o = 0.f;
        #pragma unroll 8
        for (int k = 0; k <= qi; k++) o += p[k] * vbase[(long)k * HD];
        o *= inv;
        long oidx = (long)(b * SS + qi) * DD + h * HD + t;
        bf16 hh, ll; split_bf16(o, hh, ll);
        oh[oidx] = hh; ol[oidx] = ll;
    }
}

// ======================= residual(+res2) (+GELU) + LayerNorm + split =======================
__global__ __launch_bounds__(256) void add_ln_kernel(
    const float* __restrict__ res_in, const float* __restrict__ res_in2,
    const float* __restrict__ w, const float* __restrict__ bvec,
    bf16* __restrict__ ah, bf16* __restrict__ al,
    int dogelu) {
    const int row = blockIdx.x;
    const int t = threadIdx.x;
    __shared__ float rs1[8], rs2[8];

    float vals[3];
    float s1 = 0.f, s2 = 0.f;
    #pragma unroll
    for (int i = 0; i < 3; i++) {
        int d = t + i * 256;
        float r = res_in[(long)row * DD + d] + res_in2[(long)row * DD + d];
        if (dogelu) r = 0.5f * r * (1.f + erff(r * 0.70710678118f));
        float v = g_h[(long)row * DD + d] + r;
        vals[i] = v;
        s1 += v;
        s2 += v * v;
    }
    #pragma unroll
    for (int off = 16; off > 0; off >>= 1) {
        s1 += __shfl_xor_sync(0xffffffff, s1, off);
        s2 += __shfl_xor_sync(0xffffffff, s2, off);
    }
    if ((t & 31) == 0) { rs1[t >> 5] = s1; rs2[t >> 5] = s2; }
    __syncthreads();
    if (t < 32) {
        float a = (t < 8) ? rs1[t] : 0.f;
        float bq_ = (t < 8) ? rs2[t] : 0.f;
        #pragma unroll
        for (int off = 4; off > 0; off >>= 1) {
            a  += __shfl_xor_sync(0xffffffff, a, off);
            bq_ += __shfl_xor_sync(0xffffffff, bq_, off);
        }
        if (t == 0) { rs1[0] = a; rs2[0] = bq_; }
    }
    __syncthreads();
    const float mean = rs1[0] * (1.f / DD);
    const float var  = rs2[0] * (1.f / DD) - mean * mean;
    const float rstd = rsqrtf(var + 1e-5f);

    #pragma unroll
    for (int i = 0; i < 3; i++) {
        int d = t + i * 256;
        float v = (vals[i] - mean) * rstd * w[d] + bvec[d];
        g_h[(long)row * DD + d] = v;
        bf16 hh, ll; split_bf16(v, hh, ll);
        ah[(long)row * DD + d] = hh;
        al[(long)row * DD + d] = ll;
    }
}

// ======================= host orchestration =======================
extern "C" void kernel_launch(void* const* d_in, const int* in_sizes, int n_in,
                              void* d_out, int out_size) {
    const int*   x    = (const int*)  d_in[0];
    const int*   ign  = (const int*)  d_in[1];
    const float* bpe  = (const float*)d_in[2];
    const float* pe   = (const float*)d_in[3];
    const float* Wq   = (const float*)d_in[4];
    const float* bq   = (const float*)d_in[5];
    const float* Wk   = (const float*)d_in[6];
    const float* bk   = (const float*)d_in[7];
    const float* Wv   = (const float*)d_in[8];
    const float* bv   = (const float*)d_in[9];
    const float* Wo   = (const float*)d_in[10];
    const float* bo   = (const float*)d_in[11];
    const float* W1   = (const float*)d_in[12];
    const float* b1   = (const float*)d_in[13];
    const float* W2   = (const float*)d_in[14];
    const float* b2   = (const float*)d_in[15];
    const float* ln1w = (const float*)d_in[16];
    const float* ln1b = (const float*)d_in[17];
    const float* ln2w = (const float*)d_in[18];
    const float* ln2b = (const float*)d_in[19];
    const float* Wout = (const float*)d_in[20];
    const float* bout = (const float*)d_in[21];
    float* out = (float*)d_out;

    float *gh, *gqkv, *gproj, *gff2, *gbqkv;
    cudaGetSymbolAddress((void**)&gh,    g_h);
    cudaGetSymbolAddress((void**)&gqkv,  g_qkv);
    cudaGetSymbolAddress((void**)&gproj, g_proj);
    cudaGetSymbolAddress((void**)&gff2,  g_ff2);
    cudaGetSymbolAddress((void**)&gbqkv, g_bqkv);

    bf16 *wqkv_h, *wo_h, *w1_h, *w2_h, *wout_h, *actA_h, *actB_h;
    bf16 *wqkv_l, *wo_l, *w1_l, *w2_l, *wout_l, *actA_l, *actB_l;
    void* p;
    cudaGetSymbolAddress(&p, s_wqkv); wqkv_h = (bf16*)p; wqkv_l = wqkv_h + (long)LL*3*DD*DD;
    cudaGetSymbolAddress(&p, s_wo);   wo_h = (bf16*)p;   wo_l   = wo_h   + (long)LL*DD*DD;
    cudaGetSymbolAddress(&p, s_w1);   w1_h = (bf16*)p;   w1_l   = w1_h   + (long)LL*DD*FF;
    cudaGetSymbolAddress(&p, s_w2);   w2_h = (bf16*)p;   w2_l   = w2_h   + (long)LL*FF*DD;
    cudaGetSymbolAddress(&p, s_wout); wout_h = (bf16*)p; wout_l = wout_h + (long)VV*DD;
    cudaGetSymbolAddress(&p, s_actA); actA_h = (bf16*)p; actA_l = actA_h + (long)BB*SS*FF;
    cudaGetSymbolAddress(&p, s_actB); actB_h = (bf16*)p; actB_l = actB_h + (long)BB*SS*FF;

    const int SM128 = (2*128 + 256) * TROW * 2;   // 81920
    cudaFuncSetAttribute(gemm_hmma<0>, cudaFuncAttributeMaxDynamicSharedMemorySize, SM128);
    cudaFuncSetAttribute(gemm_hmma<1>, cudaFuncAttributeMaxDynamicSharedMemorySize, SM128);
    cudaFuncSetAttribute(gemm_hmma<2>, cudaFuncAttributeMaxDynamicSharedMemorySize, SM128);

    const int M = BB * SS;   // 2048
    const long PL = (long)M * DD;
    dim3 tb32(32, 8);

    // launches: embed(0), concat(1), conv_qkv(2), QKV-gemm(3) <- ncu capture slot
    embed_kernel<<<(BB*SS*DD + 255)/256, 256>>>(x, bpe, pe, actA_h, actA_l);
    concat_bias<<<(LL*3*DD + 255)/256, 256>>>(bq, bk, bv);
    conv_qkv<<<dim3(HD/32, DD/32, 3*LL*HH), tb32>>>(Wq, Wk, Wv, wqkv_h, wqkv_l);

    gemm_hmma<2><<<dim3(M/128, (3*DD)/128, 1), 256, SM128>>>(actA_h, actA_l,
        wqkv_h, wqkv_l, gbqkv, gqkv, nullptr, nullptr, 3*DD, DD, DD, 0);

    conv_transpose<<<dim3(DD/32, DD/32, LL), tb32>>>(Wo, wo_h, wo_l,
        DD, DD, (long)DD*DD, (long)DD*DD);
    conv_transpose<<<dim3(FF/32, DD/32, LL), tb32>>>(W1, w1_h, w1_l,
        DD, FF, (long)DD*FF, (long)DD*FF);
    conv_transpose<<<dim3(DD/32, FF/32, LL), tb32>>>(W2, w2_h, w2_l,
        FF, DD, (long)FF*DD, (long)FF*DD);
    conv_transpose<<<dim3(VV/32, DD/32, 1), tb32>>>(Wout, wout_h, wout_l,
        DD, VV, 0, 0);

    for (int l = 0; l < LL; l++) {
        if (l > 0) {
            gemm_hmma<2><<<dim3(M/128, (3*DD)/128, 1), 256, SM128>>>(actA_h, actA_l,
                wqkv_h + (long)l*3*DD*DD, wqkv_l + (long)l*3*DD*DD,
                gbqkv + (long)l*3*DD, gqkv, nullptr, nullptr, 3*DD, DD, DD, 0);
        }

        attn_kernel3<<<BB*HH*SS, 128>>>(ign, actB_h, actB_l);

        // proj: split-K=2 over K=768
        gemm_hmma<0><<<dim3(M/128, DD/128, 2), 256, SM128>>>(actB_h, actB_l,
            wo_h + (long)l*DD*DD, wo_l + (long)l*DD*DD,
            bo + (long)l*DD, gproj, nullptr, nullptr, DD, DD/2, DD, PL);
        add_ln_kernel<<<M, 256>>>(gproj, gproj + PL,
                                  ln1w + (long)l*DD, ln1b + (long)l*DD,
                                  actA_h, actA_l, 0);

        gemm_hmma<1><<<dim3(M/128, FF/128, 1), 256, SM128>>>(actA_h, actA_l,
            w1_h + (long)l*DD*FF, w1_l + (long)l*DD*FF,
            b1 + (long)l*FF, nullptr, actB_h, actB_l, FF, DD, DD, 0);

        // FF2: split-K=2 over K=3072
        gemm_hmma<0><<<dim3(M/128, DD/128, 2), 256, SM128>>>(actB_h, actB_l,
            w2_h + (long)l*FF*DD, w2_l + (long)l*FF*DD,
            b2 + (long)l*DD, gff2, nullptr, nullptr, DD, FF/2, FF, PL);
        add_ln_kernel<<<M, 256>>>(gff2, gff2 + PL,
                                  ln2w + (long)l*DD, ln2b + (long)l*DD,
                                  actA_h, actA_l, 1);
    }

    gemm_hmma<0><<<dim3(M/128, (VV + 127)/128, 1), 256, SM128>>>(actA_h, actA_l,
        wout_h, wout_l, bout, out, nullptr, nullptr, VV, DD, DD, 0);
}

// round 15
// speedup vs baseline: 1.1297x; 1.1017x over previous
#include <cuda_runtime.h>
#include <cuda_bf16.h>
#include <math.h>
#include <stdint.h>

#define BB 16
#define SS 128
#define VV 40000
#define DD 768
#define HH 12
#define HD 64
#define FF 3072
#define LL 12

typedef __nv_bfloat16 bf16;

// ---------------- fp32 scratch ----------------
__device__ float g_h   [BB*SS*DD];
__device__ float g_qkv [BB*SS*3*DD];   // [which][b][h][s][e] head-contiguous
__device__ float g_proj[2*BB*SS*DD];   // split-K partials
__device__ float g_ff2 [2*BB*SS*DD];
__device__ float g_bqkv[LL*3*DD];

#define QKV_PLANE (BB*SS*DD)

// ---------------- bf16 split weights [N][K] ----------------
__device__ bf16 s_wqkv[2][LL*3*DD*DD];
__device__ bf16 s_wo  [2][LL*DD*DD];
__device__ bf16 s_w1  [2][LL*DD*FF];
__device__ bf16 s_w2  [2][LL*FF*DD];
__device__ bf16 s_wout[2][VV*DD];
__device__ bf16 s_actA[2][BB*SS*FF];
__device__ bf16 s_actB[2][BB*SS*FF];

// ======================= helpers =======================
__device__ __forceinline__ uint32_t smem_u32(const void* p) {
    uint32_t a;
    asm("{ .reg .u64 t; cvta.to.shared.u64 t, %1; cvt.u32.u64 %0, t; }" : "=r"(a) : "l"(p));
    return a;
}
__device__ __forceinline__ void cp16(uint32_t dst, const void* src) {
    asm volatile("cp.async.cg.shared.global [%0], [%1], 16;" :: "r"(dst), "l"(src) : "memory");
}
__device__ __forceinline__ void zero16(uint32_t dst) {
    asm volatile("st.shared.v4.b32 [%0], {%1,%1,%1,%1};" :: "r"(dst), "r"(0u) : "memory");
}
__device__ __forceinline__ void cp_commit() {
    asm volatile("cp.async.commit_group;" ::: "memory");
}
__device__ __forceinline__ void ldm4(uint32_t addr, uint32_t* r) {
    asm volatile("ldmatrix.sync.aligned.m8n8.x4.shared.b16 {%0,%1,%2,%3}, [%4];"
                 : "=r"(r[0]), "=r"(r[1]), "=r"(r[2]), "=r"(r[3]) : "r"(addr));
}
__device__ __forceinline__ void mma16816(float* d, const uint32_t* a, uint32_t b0, uint32_t b1) {
    asm volatile(
        "mma.sync.aligned.m16n8k16.row.col.f32.bf16.bf16.f32 "
        "{%0,%1,%2,%3}, {%4,%5,%6,%7}, {%8,%9}, {%0,%1,%2,%3};"
        : "+f"(d[0]), "+f"(d[1]), "+f"(d[2]), "+f"(d[3])
        : "r"(a[0]), "r"(a[1]), "r"(a[2]), "r"(a[3]), "r"(b0), "r"(b1));
}
__device__ __forceinline__ void split_bf16(float v, bf16& h, bf16& l) {
    h = __float2bfloat16(v);
    l = __float2bfloat16(v - __bfloat162float(h));
}

// 64B rows + XOR swizzle: 16B quad q of row r lives at r*64 + ((q ^ ((r>>1)&3))<<4)
#define ROWB 64

// ======================= small kernels =======================
__global__ void embed_kernel(const int* __restrict__ x,
                             const float* __restrict__ bpe,
                             const float* __restrict__ pe,
                             bf16* __restrict__ ah, bf16* __restrict__ al) {
    int idx = blockIdx.x * blockDim.x + threadIdx.x;
    if (idx >= BB*SS*DD) return;
    int d  = idx % DD;
    int bs = idx / DD;
    int s  = bs % SS;
    int tok = x[bs];
    float v = bpe[(long)tok*DD + d] + pe[s*DD + d];
    g_h[idx] = v;
    bf16 h, l; split_bf16(v, h, l);
    ah[idx] = h; al[idx] = l;
}

__global__ void concat_bias(const float* __restrict__ bq, const float* __restrict__ bk,
                            const float* __restrict__ bv) {
    int idx = blockIdx.x * blockDim.x + threadIdx.x;
    if (idx >= LL*3*DD) return;
    int l = idx / (3*DD), n = idx % (3*DD);
    float v;
    if (n < DD)          v = bq[l*DD + n];
    else if (n < 2*DD)   v = bk[l*DD + n - DD];
    else                 v = bv[l*DD + n - 2*DD];
    g_bqkv[idx] = v;
}

// merged QKV weight transpose+split
__global__ void conv_qkv(const float* __restrict__ Wq, const float* __restrict__ Wk,
                         const float* __restrict__ Wv,
                         bf16* __restrict__ dhi, bf16* __restrict__ dlo) {
    __shared__ float t[32][36];
    int z = blockIdx.z;
    int which = z / (LL*HH);
    int rem = z % (LL*HH);
    const float* src = (which == 0) ? Wq : ((which == 1) ? Wk : Wv);
    long zs = (long)rem * DD * HD;
    int l = rem / HH, h = rem % HH;
    long zd = (long)l*3*DD*DD + (long)which*DD*DD + (long)h*HD*DD;

    int c0 = blockIdx.x * 32, r0 = blockIdx.y * 32;
    int tx = threadIdx.x, ty = threadIdx.y;
    #pragma unroll
    for (int i = 0; i < 4; i++) {
        int row = ty + i * 8;
        t[tx][row] = src[zs + (long)(r0 + row) * HD + c0 + tx];
    }
    __syncthreads();
    int cc = ty + (tx >> 3) * 8;
    int r4 = (tx & 7) * 4;
    float4 v = *reinterpret_cast<const float4*>(&t[cc][r4]);
    bf16 h0,l0,h1,l1,h2,l2,h3,l3;
    split_bf16(v.x, h0, l0); split_bf16(v.y, h1, l1);
    split_bf16(v.z, h2, l2); split_bf16(v.w, h3, l3);
    long o = zd + (long)(c0 + cc) * DD + r0 + r4;
    __nv_bfloat162 hv0(h0, h1), hv1(h2, h3), lv0(l0, l1), lv1(l2, l3);
    uint2 hp, lp;
    hp.x = *reinterpret_cast<uint32_t*>(&hv0); hp.y = *reinterpret_cast<uint32_t*>(&hv1);
    lp.x = *reinterpret_cast<uint32_t*>(&lv0); lp.y = *reinterpret_cast<uint32_t*>(&lv1);
    *reinterpret_cast<uint2*>(&dhi[o]) = hp;
    *reinterpret_cast<uint2*>(&dlo[o]) = lp;
}

// generic transpose + split (Wo/W1/W2/Wout)
__global__ void conv_transpose(const float* __restrict__ src, bf16* __restrict__ dhi,
                               bf16* __restrict__ dlo, int R, int C,
                               long srcZ, long dstZ) {
    __shared__ float t[32][36];
    int c0 = blockIdx.x * 32, r0 = blockIdx.y * 32;
    long zs = (long)blockIdx.z * srcZ;
    long zd = (long)blockIdx.z * dstZ;
    int tx = threadIdx.x, ty = threadIdx.y;
    #pragma unroll
    for (int i = 0; i < 4; i++) {
        int row = ty + i * 8;
        t[tx][row] = src[zs + (long)(r0 + row) * C + c0 + tx];
    }
    __syncthreads();
    int cc = ty + (tx >> 3) * 8;
    int r4 = (tx & 7) * 4;
    float4 v = *reinterpret_cast<const float4*>(&t[cc][r4]);
    bf16 h0,l0,h1,l1,h2,l2,h3,l3;
    split_bf16(v.x, h0, l0); split_bf16(v.y, h1, l1);
    split_bf16(v.z, h2, l2); split_bf16(v.w, h3, l3);
    long o = zd + (long)(c0 + cc) * R + r0 + r4;
    __nv_bfloat162 hv0(h0, h1), hv1(h2, h3), lv0(l0, l1), lv1(l2, l3);
    uint2 hp, lp;
    hp.x = *reinterpret_cast<uint32_t*>(&hv0); hp.y = *reinterpret_cast<uint32_t*>(&hv1);
    lp.x = *reinterpret_cast<uint32_t*>(&lv0); lp.y = *reinterpret_cast<uint32_t*>(&lv1);
    *reinterpret_cast<uint2*>(&dhi[o]) = hp;
    *reinterpret_cast<uint2*>(&dlo[o]) = lp;
}

// ======================= HMMA split-bf16 GEMM (swizzled smem, split-K) =======================
// stage layout: Ah@0 (8KB), Al@8192, Bh@16384, Bl@24576 ; stage = 32768, 2 stages = 65536
#define A_BYTES 8192
#define STAGE   32768
#define SM128   (2*STAGE)

__device__ __forceinline__ void load_chunk(
    uint32_t base, const bf16* __restrict__ Ah, const bf16* __restrict__ Al,
    const bf16* __restrict__ Bh, const bf16* __restrict__ Bl,
    int m0, int n0, int N, int lda, int c, int tid)
{
    uint32_t bb = base + (uint32_t)(c & 1) * STAGE;
    int k0 = c << 5;
    #pragma unroll
    for (int i = 0; i < 2; i++) {
        int ci  = tid + i * 256;
        int row = ci >> 2, kq = ci & 3;
        uint32_t doff = (uint32_t)(row * ROWB + ((kq ^ ((row >> 1) & 3)) << 4));
        long aoff = (long)(m0 + row) * lda + k0 + kq * 8;
        cp16(bb + doff, Ah + aoff);
        cp16(bb + A_BYTES + doff, Al + aoff);
        int nr = n0 + row;
        if (nr < N) {
            long boff = (long)nr * lda + k0 + kq * 8;
            cp16(bb + 2*A_BYTES + doff, Bh + boff);
            cp16(bb + 3*A_BYTES + doff, Bl + boff);
        } else {
            zero16(bb + 2*A_BYTES + doff);
            zero16(bb + 3*A_BYTES + doff);
        }
    }
}

__device__ __forceinline__ long qkv_addr(int row, int col) {
    int b = row >> 7, s = row & (SS - 1);
    int which = col / DD;
    int rem = col - which * DD;
    int h = rem >> 6, e = rem & 63;
    return (long)which * QKV_PLANE + (((long)(b * HH + h) * SS + s) * HD) + e;
}

template<int OUT>
__global__ __launch_bounds__(256, 2) void gemm_hmma(
    const bf16* __restrict__ Ah, const bf16* __restrict__ Al,
    const bf16* __restrict__ Bh, const bf16* __restrict__ Bl,
    const float* __restrict__ bias, float* __restrict__ C,
    bf16* __restrict__ Oh, bf16* __restrict__ Ol,
    int N, int Kloop, int lda, long Cz)
{
    extern __shared__ char smem[];
    const uint32_t base = smem_u32(smem);
    const int tid  = threadIdx.x;
    const int lane = tid & 31;
    const int w    = tid >> 5;
    const int wm   = w & 1;
    const int wn   = w >> 1;
    const int m0 = blockIdx.x * 128, n0 = blockIdx.y * 128;
    const int nCh = Kloop >> 5;
    const int kbase = blockIdx.z * Kloop;
    Ah += kbase; Al += kbase; Bh += kbase; Bl += kbase;
    const bool addb = (blockIdx.z == 0);

    float acc[4][4][4];
    #pragma unroll
    for (int i = 0; i < 4; i++)
        #pragma unroll
        for (int j = 0; j < 4; j++)
            #pragma unroll
            for (int q = 0; q < 4; q++) acc[i][j][q] = 0.f;

    // per-lane swizzled ldmatrix addressing
    const uint32_t a_rowoff = (uint32_t)((lane & 15) * ROWB);
    const uint32_t a_s      = (uint32_t)(((lane & 15) >> 1) & 3);
    const uint32_t a_qhi    = (uint32_t)(lane >> 4);            // 0/1
    const int      b_row    = (lane & 7) + ((lane & 16) ? 8 : 0);
    const uint32_t b_rowoff = (uint32_t)(b_row * ROWB);
    const uint32_t b_s      = (uint32_t)((b_row >> 1) & 3);
    const uint32_t b_qhi    = (uint32_t)((lane & 8) ? 1 : 0);

    load_chunk(base, Ah, Al, Bh, Bl, m0, n0, N, lda, 0, tid);
    cp_commit();

    for (int c = 0; c < nCh; c++) {
        if (c + 1 < nCh) {
            load_chunk(base, Ah, Al, Bh, Bl, m0, n0, N, lda, c + 1, tid);
            cp_commit();
            asm volatile("cp.async.wait_group 1;" ::: "memory");
        } else {
            asm volatile("cp.async.wait_group 0;" ::: "memory");
        }
        __syncthreads();

        uint32_t bb = base + (uint32_t)(c & 1) * STAGE;
        uint32_t aH = bb + (uint32_t)(wm * 64) * ROWB;
        uint32_t aL = aH + A_BYTES;
        uint32_t bH = bb + 2 * A_BYTES + (uint32_t)(wn * 32) * ROWB;
        uint32_t bL = bH + A_BYTES;

        #pragma unroll
        for (int ks = 0; ks < 2; ks++) {
            const uint32_t aq = (uint32_t)(((a_qhi + 2 * ks) ^ a_s) << 4);
            const uint32_t bq_ = (uint32_t)(((b_qhi + 2 * ks) ^ b_s) << 4);
            uint32_t bh[2][4], bl[2][4];
            #pragma unroll
            for (int g = 0; g < 2; g++) {
                uint32_t go = (uint32_t)(g * 16 * ROWB);
                ldm4(bH + go + b_rowoff + bq_, bh[g]);
                ldm4(bL + go + b_rowoff + bq_, bl[g]);
            }
            #pragma unroll
            for (int mi = 0; mi < 4; mi++) {
                uint32_t mo = (uint32_t)(mi * 16 * ROWB);
                uint32_t ah[4], al[4];
                ldm4(aH + mo + a_rowoff + aq, ah);
                ldm4(aL + mo + a_rowoff + aq, al);
                #pragma unroll
                for (int ni = 0; ni < 4; ni++) {
                    const int g = ni >> 1, o = (ni & 1) * 2;
                    mma16816(acc[mi][ni], ah, bh[g][o], bh[g][o + 1]);
                    mma16816(acc[mi][ni], ah, bl[g][o], bl[g][o + 1]);
                    mma16816(acc[mi][ni], al, bh[g][o], bh[g][o + 1]);
                }
            }
        }
        __syncthreads();
    }

    // epilogue
    float* Cp = C + (long)blockIdx.z * Cz;
    #pragma unroll
    for (int mi = 0; mi < 4; mi++) {
        int row = m0 + wm * 64 + mi * 16 + (lane >> 2);
        #pragma unroll
        for (int ni = 0; ni < 4; ni++) {
            int col = n0 + wn * 32 + ni * 8 + ((lane & 3) << 1);
            if (col < N) {
                float bx = addb ? bias[col] : 0.f;
                float by = addb ? bias[col + 1] : 0.f;
                float v00 = acc[mi][ni][0] + bx, v01 = acc[mi][ni][1] + by;
                float v10 = acc[mi][ni][2] + bx, v11 = acc[mi][ni][3] + by;
                if (OUT == 0) {
                    *reinterpret_cast<float2*>(Cp + (long)row * N + col)       = make_float2(v00, v01);
                    *reinterpret_cast<float2*>(Cp + (long)(row + 8) * N + col) = make_float2(v10, v11);
                } else if (OUT == 2) {
                    long a0 = qkv_addr(row, col);
                    *reinterpret_cast<float2*>(Cp + a0)          = make_float2(v00, v01);
                    *reinterpret_cast<float2*>(Cp + a0 + 8 * HD) = make_float2(v10, v11);
                } else {
                    bf16 h0,l0,h1,l1,h2,l2,h3,l3;
                    split_bf16(v00, h0, l0); split_bf16(v01, h1, l1);
                    split_bf16(v10, h2, l2); split_bf16(v11, h3, l3);
                    *reinterpret_cast<__nv_bfloat162*>(Oh + (long)row * N + col)       = __nv_bfloat162(h0, h1);
                    *reinterpret_cast<__nv_bfloat162*>(Ol + (long)row * N + col)       = __nv_bfloat162(l0, l1);
                    *reinterpret_cast<__nv_bfloat162*>(Oh + (long)(row + 8) * N + col) = __nv_bfloat162(h2, h3);
                    *reinterpret_cast<__nv_bfloat162*>(Ol + (long)(row + 8) * N + col) = __nv_bfloat162(l2, l3);
                }
            }
        }
    }
}

// ======================= attention v3: per-query block, head-contiguous KV =======================
__global__ __launch_bounds__(128) void attn_kernel3(const int* __restrict__ ignore,
                                                    bf16* __restrict__ oh,
                                                    bf16* __restrict__ ol) {
    const int qi = blockIdx.x & (SS - 1);
    const int h  = (blockIdx.x >> 7) % HH;
    const int b  = blockIdx.x / (SS * HH);
    const int t  = threadIdx.x;

    __shared__ float qrow[HD];
    __shared__ float p[SS];
    __shared__ float red[SS];

    const long headoff = (long)(b * HH + h) * SS * HD;
    const float* Q = g_qkv + 0L * QKV_PLANE + headoff;
    const float* K = g_qkv + 1L * QKV_PLANE + headoff;
    const float* V = g_qkv + 2L * QKV_PLANE + headoff;

    if (t < HD) qrow[t] = Q[(long)qi * HD + t];
    __syncthreads();

    const bool allowed = (t <= qi) && (ignore[b * SS + t] == 0 || t == qi);
    float score = -INFINITY;
    if (allowed) {
        const float* kptr = K + (long)t * HD;
        float s = 0.f;
        #pragma unroll
        for (int e = 0; e < HD; e += 4) {
            float4 kv = *reinterpret_cast<const float4*>(kptr + e);
            s += qrow[e]*kv.x + qrow[e+1]*kv.y + qrow[e+2]*kv.z + qrow[e+3]*kv.w;
        }
        score = s * 0.125f;
    }
    red[t] = score; __syncthreads();
    for (int off = 64; off > 0; off >>= 1) {
        if (t < off) red[t] = fmaxf(red[t], red[t + off]);
        __syncthreads();
    }
    const float mx = red[0];
    __syncthreads();
    const float e = allowed ? expf(score - mx) : 0.f;
    p[t] = e; red[t] = e; __syncthreads();
    for (int off = 64; off > 0; off >>= 1) {
        if (t < off) red[t] += red[t + off];
        __syncthreads();
    }
    const float inv = 1.f / red[0];
    if (t < HD) {
        const float* vbase = V + t;
        float o = 0.f;
        #pragma unroll 8
        for (int k = 0; k <= qi; k++) o += p[k] * vbase[(long)k * HD];
        o *= inv;
        long oidx = (long)(b * SS + qi) * DD + h * HD + t;
        bf16 hh, ll; split_bf16(o, hh, ll);
        oh[oidx] = hh; ol[oidx] = ll;
    }
}

// ======================= residual(+res2) (+GELU) + LayerNorm + split =======================
__global__ __launch_bounds__(256) void add_ln_kernel(
    const float* __restrict__ res_in, const float* __restrict__ res_in2,
    const float* __restrict__ w, const float* __restrict__ bvec,
    bf16* __restrict__ ah, bf16* __restrict__ al,
    int dogelu) {
    const int row = blockIdx.x;
    const int t = threadIdx.x;
    __shared__ float rs1[8], rs2[8];

    float vals[3];
    float s1 = 0.f, s2 = 0.f;
    #pragma unroll
    for (int i = 0; i < 3; i++) {
        int d = t + i * 256;
        float r = res_in[(long)row * DD + d] + res_in2[(long)row * DD + d];
        if (dogelu) r = 0.5f * r * (1.f + erff(r * 0.70710678118f));
        float v = g_h[(long)row * DD + d] + r;
        vals[i] = v;
        s1 += v;
        s2 += v * v;
    }
    #pragma unroll
    for (int off = 16; off > 0; off >>= 1) {
        s1 += __shfl_xor_sync(0xffffffff, s1, off);
        s2 += __shfl_xor_sync(0xffffffff, s2, off);
    }
    if ((t & 31) == 0) { rs1[t >> 5] = s1; rs2[t >> 5] = s2; }
    __syncthreads();
    if (t < 32) {
        float a = (t < 8) ? rs1[t] : 0.f;
        float bq_ = (t < 8) ? rs2[t] : 0.f;
        #pragma unroll
        for (int off = 4; off > 0; off >>= 1) {
            a  += __shfl_xor_sync(0xffffffff, a, off);
            bq_ += __shfl_xor_sync(0xffffffff, bq_, off);
        }
        if (t == 0) { rs1[0] = a; rs2[0] = bq_; }
    }
    __syncthreads();
    const float mean = rs1[0] * (1.f / DD);
    const float var  = rs2[0] * (1.f / DD) - mean * mean;
    const float rstd = rsqrtf(var + 1e-5f);

    #pragma unroll
    for (int i = 0; i < 3; i++) {
        int d = t + i * 256;
        float v = (vals[i] - mean) * rstd * w[d] + bvec[d];
        g_h[(long)row * DD + d] = v;
        bf16 hh, ll; split_bf16(v, hh, ll);
        ah[(long)row * DD + d] = hh;
        al[(long)row * DD + d] = ll;
    }
}

// ======================= host orchestration =======================
extern "C" void kernel_launch(void* const* d_in, const int* in_sizes, int n_in,
                              void* d_out, int out_size) {
    const int*   x    = (const int*)  d_in[0];
    const int*   ign  = (const int*)  d_in[1];
    const float* bpe  = (const float*)d_in[2];
    const float* pe   = (const float*)d_in[3];
    const float* Wq   = (const float*)d_in[4];
    const float* bq   = (const float*)d_in[5];
    const float* Wk   = (const float*)d_in[6];
    const float* bk   = (const float*)d_in[7];
    const float* Wv   = (const float*)d_in[8];
    const float* bv   = (const float*)d_in[9];
    const float* Wo   = (const float*)d_in[10];
    const float* bo   = (const float*)d_in[11];
    const float* W1   = (const float*)d_in[12];
    const float* b1   = (const float*)d_in[13];
    const float* W2   = (const float*)d_in[14];
    const float* b2   = (const float*)d_in[15];
    const float* ln1w = (const float*)d_in[16];
    const float* ln1b = (const float*)d_in[17];
    const float* ln2w = (const float*)d_in[18];
    const float* ln2b = (const float*)d_in[19];
    const float* Wout = (const float*)d_in[20];
    const float* bout = (const float*)d_in[21];
    float* out = (float*)d_out;

    float *gh, *gqkv, *gproj, *gff2, *gbqkv;
    cudaGetSymbolAddress((void**)&gh,    g_h);
    cudaGetSymbolAddress((void**)&gqkv,  g_qkv);
    cudaGetSymbolAddress((void**)&gproj, g_proj);
    cudaGetSymbolAddress((void**)&gff2,  g_ff2);
    cudaGetSymbolAddress((void**)&gbqkv, g_bqkv);

    bf16 *wqkv_h, *wo_h, *w1_h, *w2_h, *wout_h, *actA_h, *actB_h;
    bf16 *wqkv_l, *wo_l, *w1_l, *w2_l, *wout_l, *actA_l, *actB_l;
    void* p;
    cudaGetSymbolAddress(&p, s_wqkv); wqkv_h = (bf16*)p; wqkv_l = wqkv_h + (long)LL*3*DD*DD;
    cudaGetSymbolAddress(&p, s_wo);   wo_h = (bf16*)p;   wo_l   = wo_h   + (long)LL*DD*DD;
    cudaGetSymbolAddress(&p, s_w1);   w1_h = (bf16*)p;   w1_l   = w1_h   + (long)LL*DD*FF;
    cudaGetSymbolAddress(&p, s_w2);   w2_h = (bf16*)p;   w2_l   = w2_h   + (long)LL*FF*DD;
    cudaGetSymbolAddress(&p, s_wout); wout_h = (bf16*)p; wout_l = wout_h + (long)VV*DD;
    cudaGetSymbolAddress(&p, s_actA); actA_h = (bf16*)p; actA_l = actA_h + (long)BB*SS*FF;
    cudaGetSymbolAddress(&p, s_actB); actB_h = (bf16*)p; actB_l = actB_h + (long)BB*SS*FF;

    cudaFuncSetAttribute(gemm_hmma<0>, cudaFuncAttributeMaxDynamicSharedMemorySize, SM128);
    cudaFuncSetAttribute(gemm_hmma<1>, cudaFuncAttributeMaxDynamicSharedMemorySize, SM128);
    cudaFuncSetAttribute(gemm_hmma<2>, cudaFuncAttributeMaxDynamicSharedMemorySize, SM128);

    const int M = BB * SS;   // 2048
    const long PL = (long)M * DD;
    dim3 tb32(32, 8);

    // launches: embed(0), concat(1), conv_qkv(2), QKV-gemm(3) <- ncu capture slot
    embed_kernel<<<(BB*SS*DD + 255)/256, 256>>>(x, bpe, pe, actA_h, actA_l);
    concat_bias<<<(LL*3*DD + 255)/256, 256>>>(bq, bk, bv);
    conv_qkv<<<dim3(HD/32, DD/32, 3*LL*HH), tb32>>>(Wq, Wk, Wv, wqkv_h, wqkv_l);

    gemm_hmma<2><<<dim3(M/128, (3*DD)/128, 1), 256, SM128>>>(actA_h, actA_l,
        wqkv_h, wqkv_l, gbqkv, gqkv, nullptr, nullptr, 3*DD, DD, DD, 0);

    conv_transpose<<<dim3(DD/32, DD/32, LL), tb32>>>(Wo, wo_h, wo_l,
        DD, DD, (long)DD*DD, (long)DD*DD);
    conv_transpose<<<dim3(FF/32, DD/32, LL), tb32>>>(W1, w1_h, w1_l,
        DD, FF, (long)DD*FF, (long)DD*FF);
    conv_transpose<<<dim3(DD/32, FF/32, LL), tb32>>>(W2, w2_h, w2_l,
        FF, DD, (long)FF*DD, (long)FF*DD);
    conv_transpose<<<dim3(VV/32, DD/32, 1), tb32>>>(Wout, wout_h, wout_l,
        DD, VV, 0, 0);

    for (int l = 0; l < LL; l++) {
        if (l > 0) {
            gemm_hmma<2><<<dim3(M/128, (3*DD)/128, 1), 256, SM128>>>(actA_h, actA_l,
                wqkv_h + (long)l*3*DD*DD, wqkv_l + (long)l*3*DD*DD,
                gbqkv + (long)l*3*DD, gqkv, nullptr, nullptr, 3*DD, DD, DD, 0);
        }

        attn_kernel3<<<BB*HH*SS, 128>>>(ign, actB_h, actB_l);

        // proj: split-K=2 over K=768
        gemm_hmma<0><<<dim3(M/128, DD/128, 2), 256, SM128>>>(actB_h, actB_l,
            wo_h + (long)l*DD*DD, wo_l + (long)l*DD*DD,
            bo + (long)l*DD, gproj, nullptr, nullptr, DD, DD/2, DD, PL);
        add_ln_kernel<<<M, 256>>>(gproj, gproj + PL,
                                  ln1w + (long)l*DD, ln1b + (long)l*DD,
                                  actA_h, actA_l, 0);

        gemm_hmma<1><<<dim3(M/128, FF/128, 1), 256, SM128>>>(actA_h, actA_l,
            w1_h + (long)l*DD*FF, w1_l + (long)l*DD*FF,
            b1 + (long)l*FF, nullptr, actB_h, actB_l, FF, DD, DD, 0);

        // FF2: split-K=2 over K=3072
        gemm_hmma<0><<<dim3(M/128, DD/128, 2), 256, SM128>>>(actB_h, actB_l,
            w2_h + (long)l*FF*DD, w2_l + (long)l*FF*DD,
            b2 + (long)l*DD, gff2, nullptr, nullptr, DD, FF/2, FF, PL);
        add_ln_kernel<<<M, 256>>>(gff2, gff2 + PL,
                                  ln2w + (long)l*DD, ln2b + (long)l*DD,
                                  actA_h, actA_l, 1);
    }

    gemm_hmma<0><<<dim3(M/128, (VV + 127)/128, 1), 256, SM128>>>(actA_h, actA_l,
        wout_h, wout_l, bout, out, nullptr, nullptr, VV, DD, DD, 0);
}

// round 16
// speedup vs baseline: 1.1668x; 1.0329x over previous
#include <cuda_runtime.h>
#include <cuda_bf16.h>
#include <math.h>
#include <stdint.h>

#define BB 16
#define SS 128
#define VV 40000
#define DD 768
#define HH 12
#define HD 64
#define FF 3072
#define LL 12

typedef __nv_bfloat16 bf16;

// ---------------- fp32 scratch ----------------
__device__ float g_h   [BB*SS*DD];
__device__ float g_qkv [BB*SS*3*DD];   // [which][b][h][s][e] head-contiguous
__device__ float g_proj[2*BB*SS*DD];   // split-K partials
__device__ float g_ff2 [2*BB*SS*DD];
__device__ float g_bqkv[LL*3*DD];

#define QKV_PLANE (BB*SS*DD)

// ---------------- bf16 split weights [N][K] ----------------
__device__ bf16 s_wqkv[2][LL*3*DD*DD];
__device__ bf16 s_wo  [2][LL*DD*DD];
__device__ bf16 s_w1  [2][LL*DD*FF];
__device__ bf16 s_w2  [2][LL*FF*DD];
__device__ bf16 s_wout[2][VV*DD];
__device__ bf16 s_actA[2][BB*SS*FF];
__device__ bf16 s_actB[2][BB*SS*FF];

// ======================= helpers =======================
__device__ __forceinline__ uint32_t smem_u32(const void* p) {
    uint32_t a;
    asm("{ .reg .u64 t; cvta.to.shared.u64 t, %1; cvt.u32.u64 %0, t; }" : "=r"(a) : "l"(p));
    return a;
}
__device__ __forceinline__ void cp16(uint32_t dst, const void* src) {
    asm volatile("cp.async.cg.shared.global [%0], [%1], 16;" :: "r"(dst), "l"(src) : "memory");
}
__device__ __forceinline__ void zero16(uint32_t dst) {
    asm volatile("st.shared.v4.b32 [%0], {%1,%1,%1,%1};" :: "r"(dst), "r"(0u) : "memory");
}
__device__ __forceinline__ void cp_commit() {
    asm volatile("cp.async.commit_group;" ::: "memory");
}
__device__ __forceinline__ void ldm4(uint32_t addr, uint32_t* r) {
    asm volatile("ldmatrix.sync.aligned.m8n8.x4.shared.b16 {%0,%1,%2,%3}, [%4];"
                 : "=r"(r[0]), "=r"(r[1]), "=r"(r[2]), "=r"(r[3]) : "r"(addr));
}
__device__ __forceinline__ void mma16816(float* d, const uint32_t* a, uint32_t b0, uint32_t b1) {
    asm volatile(
        "mma.sync.aligned.m16n8k16.row.col.f32.bf16.bf16.f32 "
        "{%0,%1,%2,%3}, {%4,%5,%6,%7}, {%8,%9}, {%0,%1,%2,%3};"
        : "+f"(d[0]), "+f"(d[1]), "+f"(d[2]), "+f"(d[3])
        : "r"(a[0]), "r"(a[1]), "r"(a[2]), "r"(a[3]), "r"(b0), "r"(b1));
}
__device__ __forceinline__ void split_bf16(float v, bf16& h, bf16& l) {
    h = __float2bfloat16(v);
    l = __float2bfloat16(v - __bfloat162float(h));
}

// 64B rows + XOR swizzle: 16B quad q of row r lives at r*64 + ((q ^ ((r>>1)&3))<<4)
#define ROWB 64

// ======================= small kernels =======================
__global__ void embed_kernel(const int* __restrict__ x,
                             const float* __restrict__ bpe,
                             const float* __restrict__ pe,
                             bf16* __restrict__ ah, bf16* __restrict__ al) {
    int idx = blockIdx.x * blockDim.x + threadIdx.x;
    if (idx >= BB*SS*DD) return;
    int d  = idx % DD;
    int bs = idx / DD;
    int s  = bs % SS;
    int tok = x[bs];
    float v = bpe[(long)tok*DD + d] + pe[s*DD + d];
    g_h[idx] = v;
    bf16 h, l; split_bf16(v, h, l);
    ah[idx] = h; al[idx] = l;
}

__global__ void concat_bias(const float* __restrict__ bq, const float* __restrict__ bk,
                            const float* __restrict__ bv) {
    int idx = blockIdx.x * blockDim.x + threadIdx.x;
    if (idx >= LL*3*DD) return;
    int l = idx / (3*DD), n = idx % (3*DD);
    float v;
    if (n < DD)          v = bq[l*DD + n];
    else if (n < 2*DD)   v = bk[l*DD + n - DD];
    else                 v = bv[l*DD + n - 2*DD];
    g_bqkv[idx] = v;
}

// merged QKV weight transpose+split
__global__ void conv_qkv(const float* __restrict__ Wq, const float* __restrict__ Wk,
                         const float* __restrict__ Wv,
                         bf16* __restrict__ dhi, bf16* __restrict__ dlo) {
    __shared__ float t[32][36];
    int z = blockIdx.z;
    int which = z / (LL*HH);
    int rem = z % (LL*HH);
    const float* src = (which == 0) ? Wq : ((which == 1) ? Wk : Wv);
    long zs = (long)rem * DD * HD;
    int l = rem / HH, h = rem % HH;
    long zd = (long)l*3*DD*DD + (long)which*DD*DD + (long)h*HD*DD;

    int c0 = blockIdx.x * 32, r0 = blockIdx.y * 32;
    int tx = threadIdx.x, ty = threadIdx.y;
    #pragma unroll
    for (int i = 0; i < 4; i++) {
        int row = ty + i * 8;
        t[tx][row] = src[zs + (long)(r0 + row) * HD + c0 + tx];
    }
    __syncthreads();
    int cc = ty + (tx >> 3) * 8;
    int r4 = (tx & 7) * 4;
    float4 v = *reinterpret_cast<const float4*>(&t[cc][r4]);
    bf16 h0,l0,h1,l1,h2,l2,h3,l3;
    split_bf16(v.x, h0, l0); split_bf16(v.y, h1, l1);
    split_bf16(v.z, h2, l2); split_bf16(v.w, h3, l3);
    long o = zd + (long)(c0 + cc) * DD + r0 + r4;
    __nv_bfloat162 hv0(h0, h1), hv1(h2, h3), lv0(l0, l1), lv1(l2, l3);
    uint2 hp, lp;
    hp.x = *reinterpret_cast<uint32_t*>(&hv0); hp.y = *reinterpret_cast<uint32_t*>(&hv1);
    lp.x = *reinterpret_cast<uint32_t*>(&lv0); lp.y = *reinterpret_cast<uint32_t*>(&lv1);
    *reinterpret_cast<uint2*>(&dhi[o]) = hp;
    *reinterpret_cast<uint2*>(&dlo[o]) = lp;
}

// generic transpose + split (Wo/W1/W2/Wout)
__global__ void conv_transpose(const float* __restrict__ src, bf16* __restrict__ dhi,
                               bf16* __restrict__ dlo, int R, int C,
                               long srcZ, long dstZ) {
    __shared__ float t[32][36];
    int c0 = blockIdx.x * 32, r0 = blockIdx.y * 32;
    long zs = (long)blockIdx.z * srcZ;
    long zd = (long)blockIdx.z * dstZ;
    int tx = threadIdx.x, ty = threadIdx.y;
    #pragma unroll
    for (int i = 0; i < 4; i++) {
        int row = ty + i * 8;
        t[tx][row] = src[zs + (long)(r0 + row) * C + c0 + tx];
    }
    __syncthreads();
    int cc = ty + (tx >> 3) * 8;
    int r4 = (tx & 7) * 4;
    float4 v = *reinterpret_cast<const float4*>(&t[cc][r4]);
    bf16 h0,l0,h1,l1,h2,l2,h3,l3;
    split_bf16(v.x, h0, l0); split_bf16(v.y, h1, l1);
    split_bf16(v.z, h2, l2); split_bf16(v.w, h3, l3);
    long o = zd + (long)(c0 + cc) * R + r0 + r4;
    __nv_bfloat162 hv0(h0, h1), hv1(h2, h3), lv0(l0, l1), lv1(l2, l3);
    uint2 hp, lp;
    hp.x = *reinterpret_cast<uint32_t*>(&hv0); hp.y = *reinterpret_cast<uint32_t*>(&hv1);
    lp.x = *reinterpret_cast<uint32_t*>(&lv0); lp.y = *reinterpret_cast<uint32_t*>(&lv1);
    *reinterpret_cast<uint2*>(&dhi[o]) = hp;
    *reinterpret_cast<uint2*>(&dlo[o]) = lp;
}

// ======================= HMMA split-bf16 GEMM (swizzled smem, split-K) =======================
#define A_BYTES 8192
#define STAGE   32768
#define SM128   (2*STAGE)

__device__ __forceinline__ void load_chunk(
    uint32_t base, const bf16* __restrict__ Ah, const bf16* __restrict__ Al,
    const bf16* __restrict__ Bh, const bf16* __restrict__ Bl,
    int m0, int n0, int N, int lda, int c, int tid)
{
    uint32_t bb = base + (uint32_t)(c & 1) * STAGE;
    int k0 = c << 5;
    #pragma unroll
    for (int i = 0; i < 2; i++) {
        int ci  = tid + i * 256;
        int row = ci >> 2, kq = ci & 3;
        uint32_t doff = (uint32_t)(row * ROWB + ((kq ^ ((row >> 1) & 3)) << 4));
        long aoff = (long)(m0 + row) * lda + k0 + kq * 8;
        cp16(bb + doff, Ah + aoff);
        cp16(bb + A_BYTES + doff, Al + aoff);
        int nr = n0 + row;
        if (nr < N) {
            long boff = (long)nr * lda + k0 + kq * 8;
            cp16(bb + 2*A_BYTES + doff, Bh + boff);
            cp16(bb + 3*A_BYTES + doff, Bl + boff);
        } else {
            zero16(bb + 2*A_BYTES + doff);
            zero16(bb + 3*A_BYTES + doff);
        }
    }
}

__device__ __forceinline__ long qkv_addr(int row, int col) {
    int b = row >> 7, s = row & (SS - 1);
    int which = col / DD;
    int rem = col - which * DD;
    int h = rem >> 6, e = rem & 63;
    return (long)which * QKV_PLANE + (((long)(b * HH + h) * SS + s) * HD) + e;
}

template<int OUT>
__global__ __launch_bounds__(256, 2) void gemm_hmma(
    const bf16* __restrict__ Ah, const bf16* __restrict__ Al,
    const bf16* __restrict__ Bh, const bf16* __restrict__ Bl,
    const float* __restrict__ bias, float* __restrict__ C,
    bf16* __restrict__ Oh, bf16* __restrict__ Ol,
    int N, int Kloop, int lda, long Cz)
{
    extern __shared__ char smem[];
    const uint32_t base = smem_u32(smem);
    const int tid  = threadIdx.x;
    const int lane = tid & 31;
    const int w    = tid >> 5;
    const int wm   = w & 1;
    const int wn   = w >> 1;
    const int m0 = blockIdx.x * 128, n0 = blockIdx.y * 128;
    const int nCh = Kloop >> 5;
    const int kbase = blockIdx.z * Kloop;
    Ah += kbase; Al += kbase; Bh += kbase; Bl += kbase;
    const bool addb = (blockIdx.z == 0);

    float acc[4][4][4];
    #pragma unroll
    for (int i = 0; i < 4; i++)
        #pragma unroll
        for (int j = 0; j < 4; j++)
            #pragma unroll
            for (int q = 0; q < 4; q++) acc[i][j][q] = 0.f;

    const uint32_t a_rowoff = (uint32_t)((lane & 15) * ROWB);
    const uint32_t a_s      = (uint32_t)(((lane & 15) >> 1) & 3);
    const uint32_t a_qhi    = (uint32_t)(lane >> 4);
    const int      b_row    = (lane & 7) + ((lane & 16) ? 8 : 0);
    const uint32_t b_rowoff = (uint32_t)(b_row * ROWB);
    const uint32_t b_s      = (uint32_t)((b_row >> 1) & 3);
    const uint32_t b_qhi    = (uint32_t)((lane & 8) ? 1 : 0);

    load_chunk(base, Ah, Al, Bh, Bl, m0, n0, N, lda, 0, tid);
    cp_commit();

    for (int c = 0; c < nCh; c++) {
        if (c + 1 < nCh) {
            load_chunk(base, Ah, Al, Bh, Bl, m0, n0, N, lda, c + 1, tid);
            cp_commit();
            asm volatile("cp.async.wait_group 1;" ::: "memory");
        } else {
            asm volatile("cp.async.wait_group 0;" ::: "memory");
        }
        __syncthreads();

        uint32_t bb = base + (uint32_t)(c & 1) * STAGE;
        uint32_t aH = bb + (uint32_t)(wm * 64) * ROWB;
        uint32_t aL = aH + A_BYTES;
        uint32_t bH = bb + 2 * A_BYTES + (uint32_t)(wn * 32) * ROWB;
        uint32_t bL = bH + A_BYTES;

        #pragma unroll
        for (int ks = 0; ks < 2; ks++) {
            const uint32_t aq = (uint32_t)(((a_qhi + 2 * ks) ^ a_s) << 4);
            const uint32_t bq_ = (uint32_t)(((b_qhi + 2 * ks) ^ b_s) << 4);
            uint32_t bh[2][4], bl[2][4];
            #pragma unroll
            for (int g = 0; g < 2; g++) {
                uint32_t go = (uint32_t)(g * 16 * ROWB);
                ldm4(bH + go + b_rowoff + bq_, bh[g]);
                ldm4(bL + go + b_rowoff + bq_, bl[g]);
            }
            #pragma unroll
            for (int mi = 0; mi < 4; mi++) {
                uint32_t mo = (uint32_t)(mi * 16 * ROWB);
                uint32_t ah[4], al[4];
                ldm4(aH + mo + a_rowoff + aq, ah);
                ldm4(aL + mo + a_rowoff + aq, al);
                #pragma unroll
                for (int ni = 0; ni < 4; ni++) {
                    const int g = ni >> 1, o = (ni & 1) * 2;
                    mma16816(acc[mi][ni], ah, bh[g][o], bh[g][o + 1]);
                    mma16816(acc[mi][ni], ah, bl[g][o], bl[g][o + 1]);
                    mma16816(acc[mi][ni], al, bh[g][o], bh[g][o + 1]);
                }
            }
        }
        __syncthreads();
    }

    // epilogue
    float* Cp = C + (long)blockIdx.z * Cz;
    #pragma unroll
    for (int mi = 0; mi < 4; mi++) {
        int row = m0 + wm * 64 + mi * 16 + (lane >> 2);
        #pragma unroll
        for (int ni = 0; ni < 4; ni++) {
            int col = n0 + wn * 32 + ni * 8 + ((lane & 3) << 1);
            if (col < N) {
                float bx = addb ? bias[col] : 0.f;
                float by = addb ? bias[col + 1] : 0.f;
                float v00 = acc[mi][ni][0] + bx, v01 = acc[mi][ni][1] + by;
                float v10 = acc[mi][ni][2] + bx, v11 = acc[mi][ni][3] + by;
                if (OUT == 0) {
                    *reinterpret_cast<float2*>(Cp + (long)row * N + col)       = make_float2(v00, v01);
                    *reinterpret_cast<float2*>(Cp + (long)(row + 8) * N + col) = make_float2(v10, v11);
                } else if (OUT == 2) {
                    long a0 = qkv_addr(row, col);
                    *reinterpret_cast<float2*>(Cp + a0)          = make_float2(v00, v01);
                    *reinterpret_cast<float2*>(Cp + a0 + 8 * HD) = make_float2(v10, v11);
                } else {
                    bf16 h0,l0,h1,l1,h2,l2,h3,l3;
                    split_bf16(v00, h0, l0); split_bf16(v01, h1, l1);
                    split_bf16(v10, h2, l2); split_bf16(v11, h3, l3);
                    *reinterpret_cast<__nv_bfloat162*>(Oh + (long)row * N + col)       = __nv_bfloat162(h0, h1);
                    *reinterpret_cast<__nv_bfloat162*>(Ol + (long)row * N + col)       = __nv_bfloat162(l0, l1);
                    *reinterpret_cast<__nv_bfloat162*>(Oh + (long)(row + 8) * N + col) = __nv_bfloat162(h2, h3);
                    *reinterpret_cast<__nv_bfloat162*>(Ol + (long)(row + 8) * N + col) = __nv_bfloat162(l2, l3);
                }
            }
        }
    }
}

// ======================= attention v5: flash-style q-tile of 16, smem K/V =======================
// grid (8, HH, BB), 256 threads. smem: kv[128*64] (K then V) | ps[16*128] | qs[16*64] | keep[128]
#define ATT5_SMEM ((SS*HD + 16*SS + 16*HD) * 4 + SS * 4)

__global__ __launch_bounds__(256) void attn_kernel5(const int* __restrict__ ignore,
                                                    bf16* __restrict__ oh,
                                                    bf16* __restrict__ ol) {
    extern __shared__ float sm[];
    float* kv = sm;                    // 8192 floats: K, later V
    float* ps = sm + SS*HD;            // 2048 floats
    float* qs = ps + 16*SS;            // 1024 floats
    int*   keep = (int*)(qs + 16*HD);
    const int qt = blockIdx.x;         // 0..7
    const int h  = blockIdx.y;
    const int b  = blockIdx.z;
    const int t  = threadIdx.x;
    const long headoff = (long)(b*HH + h) * SS * HD;
    const float* Q = g_qkv + headoff;
    const float* K = g_qkv + (long)QKV_PLANE + headoff;
    const float* V = g_qkv + 2L*QKV_PLANE + headoff;
    const int q0 = qt * 16;

    // stage K (128x64 fp32) + q rows (16x64) + keep flags
    #pragma unroll
    for (int i = 0; i < 8; i++) {
        int idx = t + i * 256;
        int row = idx >> 4, f4 = (idx & 15) << 2;
        *reinterpret_cast<float4*>(&kv[row*HD + f4]) =
            *reinterpret_cast<const float4*>(&K[(long)row*HD + f4]);
    }
    {
        int row = t >> 4, f4 = (t & 15) << 2;
        *reinterpret_cast<float4*>(&qs[row*HD + f4]) =
            *reinterpret_cast<const float4*>(&Q[(long)(q0 + row)*HD + f4]);
    }
    if (t < SS) keep[t] = (ignore[b*SS + t] == 0);
    __syncthreads();

    const int ql  = t >> 4;            // 0..15 query within tile
    const int sub = t & 15;            // 16 threads per query
    const int qg  = q0 + ql;           // global query index
    const float* qr = &qs[ql*HD];

    // scores: 8 keys per thread
    float sc[8];
    #pragma unroll
    for (int j = 0; j < 8; j++) {
        int k = sub*8 + j;
        float s = -INFINITY;
        if ((k <= qg) && (keep[k] || k == qg)) {
            const float* kr = &kv[k*HD];
            float d = 0.f;
            #pragma unroll
            for (int e = 0; e < HD; e += 4) {
                float4 kvv = *reinterpret_cast<const float4*>(kr + e);
                d += qr[e]*kvv.x + qr[e+1]*kvv.y + qr[e+2]*kvv.z + qr[e+3]*kvv.w;
            }
            s = d * 0.125f;
        }
        sc[j] = s;
    }
    // softmax within 16-lane group (shuffle only)
    float m = sc[0];
    #pragma unroll
    for (int j = 1; j < 8; j++) m = fmaxf(m, sc[j]);
    #pragma unroll
    for (int off = 8; off > 0; off >>= 1)
        m = fmaxf(m, __shfl_xor_sync(0xffffffffu, m, off));
    float sum = 0.f;
    #pragma unroll
    for (int j = 0; j < 8; j++) {
        float e = expf(sc[j] - m);     // exp(-inf)=0
        ps[ql*SS + sub*8 + j] = e;
        sum += e;
    }
    #pragma unroll
    for (int off = 8; off > 0; off >>= 1)
        sum += __shfl_xor_sync(0xffffffffu, sum, off);
    const float inv = 1.f / sum;
    __syncthreads();                   // scores done reading K

    // V overwrites K region
    #pragma unroll
    for (int i = 0; i < 8; i++) {
        int idx = t + i * 256;
        int row = idx >> 4, f4 = (idx & 15) << 2;
        *reinterpret_cast<float4*>(&kv[row*HD + f4]) =
            *reinterpret_cast<const float4*>(&V[(long)row*HD + f4]);
    }
    __syncthreads();

    // AV: thread -> (ql, 4 e-slots), k bounded by qg
    const float* pr = &ps[ql*SS];
    const int e4 = sub * 4;
    float o0=0.f, o1=0.f, o2=0.f, o3=0.f;
    for (int k = 0; k <= qg; k++) {
        float pk = pr[k];
        float4 vv = *reinterpret_cast<const float4*>(&kv[k*HD + e4]);
        o0 += pk*vv.x; o1 += pk*vv.y; o2 += pk*vv.z; o3 += pk*vv.w;
    }
    o0*=inv; o1*=inv; o2*=inv; o3*=inv;
    long oidx = (long)(b*SS + qg) * DD + h*HD + e4;
    bf16 h0,l0,h1,l1,h2,l2,h3,l3;
    split_bf16(o0,h0,l0); split_bf16(o1,h1,l1);
    split_bf16(o2,h2,l2); split_bf16(o3,h3,l3);
    *reinterpret_cast<__nv_bfloat162*>(&oh[oidx])     = __nv_bfloat162(h0,h1);
    *reinterpret_cast<__nv_bfloat162*>(&oh[oidx + 2]) = __nv_bfloat162(h2,h3);
    *reinterpret_cast<__nv_bfloat162*>(&ol[oidx])     = __nv_bfloat162(l0,l1);
    *reinterpret_cast<__nv_bfloat162*>(&ol[oidx + 2]) = __nv_bfloat162(l2,l3);
}

// ======================= residual(+res2) (+GELU) + LayerNorm + split =======================
__global__ __launch_bounds__(256) void add_ln_kernel(
    const float* __restrict__ res_in, const float* __restrict__ res_in2,
    const float* __restrict__ w, const float* __restrict__ bvec,
    bf16* __restrict__ ah, bf16* __restrict__ al,
    int dogelu) {
    const int row = blockIdx.x;
    const int t = threadIdx.x;
    __shared__ float rs1[8], rs2[8];

    float vals[3];
    float s1 = 0.f, s2 = 0.f;
    #pragma unroll
    for (int i = 0; i < 3; i++) {
        int d = t + i * 256;
        float r = res_in[(long)row * DD + d] + res_in2[(long)row * DD + d];
        if (dogelu) r = 0.5f * r * (1.f + erff(r * 0.70710678118f));
        float v = g_h[(long)row * DD + d] + r;
        vals[i] = v;
        s1 += v;
        s2 += v * v;
    }
    #pragma unroll
    for (int off = 16; off > 0; off >>= 1) {
        s1 += __shfl_xor_sync(0xffffffff, s1, off);
        s2 += __shfl_xor_sync(0xffffffff, s2, off);
    }
    if ((t & 31) == 0) { rs1[t >> 5] = s1; rs2[t >> 5] = s2; }
    __syncthreads();
    if (t < 32) {
        float a = (t < 8) ? rs1[t] : 0.f;
        float bq_ = (t < 8) ? rs2[t] : 0.f;
        #pragma unroll
        for (int off = 4; off > 0; off >>= 1) {
            a  += __shfl_xor_sync(0xffffffff, a, off);
            bq_ += __shfl_xor_sync(0xffffffff, bq_, off);
        }
        if (t == 0) { rs1[0] = a; rs2[0] = bq_; }
    }
    __syncthreads();
    const float mean = rs1[0] * (1.f / DD);
    const float var  = rs2[0] * (1.f / DD) - mean * mean;
    const float rstd = rsqrtf(var + 1e-5f);

    #pragma unroll
    for (int i = 0; i < 3; i++) {
        int d = t + i * 256;
        float v = (vals[i] - mean) * rstd * w[d] + bvec[d];
        g_h[(long)row * DD + d] = v;
        bf16 hh, ll; split_bf16(v, hh, ll);
        ah[(long)row * DD + d] = hh;
        al[(long)row * DD + d] = ll;
    }
}

// ======================= host orchestration =======================
extern "C" void kernel_launch(void* const* d_in, const int* in_sizes, int n_in,
                              void* d_out, int out_size) {
    const int*   x    = (const int*)  d_in[0];
    const int*   ign  = (const int*)  d_in[1];
    const float* bpe  = (const float*)d_in[2];
    const float* pe   = (const float*)d_in[3];
    const float* Wq   = (const float*)d_in[4];
    const float* bq   = (const float*)d_in[5];
    const float* Wk   = (const float*)d_in[6];
    const float* bk   = (const float*)d_in[7];
    const float* Wv   = (const float*)d_in[8];
    const float* bv   = (const float*)d_in[9];
    const float* Wo   = (const float*)d_in[10];
    const float* bo   = (const float*)d_in[11];
    const float* W1   = (const float*)d_in[12];
    const float* b1   = (const float*)d_in[13];
    const float* W2   = (const float*)d_in[14];
    const float* b2   = (const float*)d_in[15];
    const float* ln1w = (const float*)d_in[16];
    const float* ln1b = (const float*)d_in[17];
    const float* ln2w = (const float*)d_in[18];
    const float* ln2b = (const float*)d_in[19];
    const float* Wout = (const float*)d_in[20];
    const float* bout = (const float*)d_in[21];
    float* out = (float*)d_out;

    float *gh, *gqkv, *gproj, *gff2, *gbqkv;
    cudaGetSymbolAddress((void**)&gh,    g_h);
    cudaGetSymbolAddress((void**)&gqkv,  g_qkv);
    cudaGetSymbolAddress((void**)&gproj, g_proj);
    cudaGetSymbolAddress((void**)&gff2,  g_ff2);
    cudaGetSymbolAddress((void**)&gbqkv, g_bqkv);

    bf16 *wqkv_h, *wo_h, *w1_h, *w2_h, *wout_h, *actA_h, *actB_h;
    bf16 *wqkv_l, *wo_l, *w1_l, *w2_l, *wout_l, *actA_l, *actB_l;
    void* p;
    cudaGetSymbolAddress(&p, s_wqkv); wqkv_h = (bf16*)p; wqkv_l = wqkv_h + (long)LL*3*DD*DD;
    cudaGetSymbolAddress(&p, s_wo);   wo_h = (bf16*)p;   wo_l   = wo_h   + (long)LL*DD*DD;
    cudaGetSymbolAddress(&p, s_w1);   w1_h = (bf16*)p;   w1_l   = w1_h   + (long)LL*DD*FF;
    cudaGetSymbolAddress(&p, s_w2);   w2_h = (bf16*)p;   w2_l   = w2_h   + (long)LL*FF*DD;
    cudaGetSymbolAddress(&p, s_wout); wout_h = (bf16*)p; wout_l = wout_h + (long)VV*DD;
    cudaGetSymbolAddress(&p, s_actA); actA_h = (bf16*)p; actA_l = actA_h + (long)BB*SS*FF;
    cudaGetSymbolAddress(&p, s_actB); actB_h = (bf16*)p; actB_l = actB_h + (long)BB*SS*FF;

    cudaFuncSetAttribute(gemm_hmma<0>, cudaFuncAttributeMaxDynamicSharedMemorySize, SM128);
    cudaFuncSetAttribute(gemm_hmma<1>, cudaFuncAttributeMaxDynamicSharedMemorySize, SM128);
    cudaFuncSetAttribute(gemm_hmma<2>, cudaFuncAttributeMaxDynamicSharedMemorySize, SM128);

    const int M = BB * SS;   // 2048
    const long PL = (long)M * DD;
    dim3 tb32(32, 8);

    // launches: embed(0), concat(1), conv_qkv(2), QKV-gemm(3) <- ncu capture slot
    embed_kernel<<<(BB*SS*DD + 255)/256, 256>>>(x, bpe, pe, actA_h, actA_l);
    concat_bias<<<(LL*3*DD + 255)/256, 256>>>(bq, bk, bv);
    conv_qkv<<<dim3(HD/32, DD/32, 3*LL*HH), tb32>>>(Wq, Wk, Wv, wqkv_h, wqkv_l);

    gemm_hmma<2><<<dim3(M/128, (3*DD)/128, 1), 256, SM128>>>(actA_h, actA_l,
        wqkv_h, wqkv_l, gbqkv, gqkv, nullptr, nullptr, 3*DD, DD, DD, 0);

    conv_transpose<<<dim3(DD/32, DD/32, LL), tb32>>>(Wo, wo_h, wo_l,
        DD, DD, (long)DD*DD, (long)DD*DD);
    conv_transpose<<<dim3(FF/32, DD/32, LL), tb32>>>(W1, w1_h, w1_l,
        DD, FF, (long)DD*FF, (long)DD*FF);
    conv_transpose<<<dim3(DD/32, FF/32, LL), tb32>>>(W2, w2_h, w2_l,
        FF, DD, (long)FF*DD, (long)FF*DD);
    conv_transpose<<<dim3(VV/32, DD/32, 1), tb32>>>(Wout, wout_h, wout_l,
        DD, VV, 0, 0);

    for (int l = 0; l < LL; l++) {
        if (l > 0) {
            gemm_hmma<2><<<dim3(M/128, (3*DD)/128, 1), 256, SM128>>>(actA_h, actA_l,
                wqkv_h + (long)l*3*DD*DD, wqkv_l + (long)l*3*DD*DD,
                gbqkv + (long)l*3*DD, gqkv, nullptr, nullptr, 3*DD, DD, DD, 0);
        }

        attn_kernel5<<<dim3(SS/16, HH, BB), 256, ATT5_SMEM>>>(ign, actB_h, actB_l);

        // proj: split-K=2 over K=768
        gemm_hmma<0><<<dim3(M/128, DD/128, 2), 256, SM128>>>(actB_h, actB_l,
            wo_h + (long)l*DD*DD, wo_l + (long)l*DD*DD,
            bo + (long)l*DD, gproj, nullptr, nullptr, DD, DD/2, DD, PL);
        add_ln_kernel<<<M, 256>>>(gproj, gproj + PL,
                                  ln1w + (long)l*DD, ln1b + (long)l*DD,
                                  actA_h, actA_l, 0);

        gemm_hmma<1><<<dim3(M/128, FF/128, 1), 256, SM128>>>(actA_h, actA_l,
            w1_h + (long)l*DD*FF, w1_l + (long)l*DD*FF,
            b1 + (long)l*FF, nullptr, actB_h, actB_l, FF, DD, DD, 0);

        // FF2: split-K=2 over K=3072
        gemm_hmma<0><<<dim3(M/128, DD/128, 2), 256, SM128>>>(actB_h, actB_l,
            w2_h + (long)l*FF*DD, w2_l + (long)l*FF*DD,
            b2 + (long)l*DD, gff2, nullptr, nullptr, DD, FF/2, FF, PL);
        add_ln_kernel<<<M, 256>>>(gff2, gff2 + PL,
                                  ln2w + (long)l*DD, ln2b + (long)l*DD,
                                  actA_h, actA_l, 1);
    }

    gemm_hmma<0><<<dim3(M/128, (VV + 127)/128, 1), 256, SM128>>>(actA_h, actA_l,
        wout_h, wout_l, bout, out, nullptr, nullptr, VV, DD, DD, 0);
}